// round 5
// baseline (speedup 1.0000x reference)
#include <cuda_runtime.h>
#include <math.h>

#define N_B   2
#define C_DIM 512
#define S_TOT 13294
#define FL_N  4

// Level geometry (H, W, flat offset in s)
__constant__ int c_H[4]   = {100, 50, 25, 13};
__constant__ int c_W[4]   = {100, 50, 25, 13};
__constant__ int c_off[4] = {0, 10000, 12500, 13125};

// Scratch: value transposed (n, s, c) and sampled pre-output (n, s, c)
__device__ __align__(16) float g_value[N_B * S_TOT * C_DIM];
__device__ __align__(16) float g_pre[N_B * S_TOT * C_DIM];

// ---- f32x2 helpers (Blackwell packed fp32) ----
__device__ __forceinline__ unsigned long long dup2(float v) {
    unsigned int u = __float_as_uint(v);
    unsigned long long r;
    asm("mov.b64 %0, {%1, %1};" : "=l"(r) : "r"(u));
    return r;
}
__device__ __forceinline__ void ffma2(unsigned long long& d, unsigned long long a, unsigned long long b) {
    asm("fma.rn.f32x2 %0, %1, %2, %0;" : "+l"(d) : "l"(a), "l"(b));
}
__device__ __forceinline__ float plo(unsigned long long v) { return __uint_as_float((unsigned int)v); }
__device__ __forceinline__ float phi(unsigned long long v) { return __uint_as_float((unsigned int)(v >> 32)); }

// =====================================================================
// Kernel A: g_value[n][s][c] = mask ? 0 : sum_k Wv[c][k]*x[n][k][s] + bv[c]
// 128(s) x 128(c) tile, 256 threads, 8x8 micro, f32x2 packed along c.
// =====================================================================
__global__ void __launch_bounds__(256) k_value(
    const float* __restrict__ x, const unsigned char* __restrict__ mask,
    const float* __restrict__ Wv, const float* __restrict__ bv)
{
    __shared__ __align__(16) float Ws[16][128];   // [k][c]
    __shared__ __align__(16) float Xs[16][128];   // [k][s]
    const int sb = blockIdx.x * 128;
    const int cb = blockIdx.y * 128;
    const int n  = blockIdx.z;
    const int t  = threadIdx.x;
    const int tx = t & 15, ty = t >> 4;
    const float* xn = x + (size_t)n * C_DIM * S_TOT;

    unsigned long long acc[8][4];
#pragma unroll
    for (int i = 0; i < 8; i++)
#pragma unroll
        for (int j = 0; j < 4; j++) acc[i][j] = 0ULL;

    for (int k0 = 0; k0 < C_DIM; k0 += 16) {
#pragma unroll
        for (int i = 0; i < 2; i++) {              // Wv tile -> transpose into smem
            int u = t + i * 256;
            int cc = u >> 2, kq = u & 3;
            float4 w = *(const float4*)(Wv + (size_t)(cb + cc) * C_DIM + k0 + kq * 4);
            Ws[kq * 4 + 0][cc] = w.x;
            Ws[kq * 4 + 1][cc] = w.y;
            Ws[kq * 4 + 2][cc] = w.z;
            Ws[kq * 4 + 3][cc] = w.w;
        }
#pragma unroll
        for (int i = 0; i < 4; i++) {              // x tile (rows 8B-aligned, float2)
            int u = t + i * 256;
            int kk = u >> 6, sq = u & 63;
            int s = sb + sq * 2;
            float2 v;
            if (s + 1 < S_TOT) {
                v = *(const float2*)(xn + (size_t)(k0 + kk) * S_TOT + s);
            } else {
                v.x = (s < S_TOT) ? xn[(size_t)(k0 + kk) * S_TOT + s] : 0.0f;
                v.y = 0.0f;
            }
            *(float2*)&Xs[kk][sq * 2] = v;
        }
        __syncthreads();
#pragma unroll
        for (int kk = 0; kk < 16; kk++) {
            ulonglong2 A0 = *(const ulonglong2*)&Ws[kk][tx * 4];
            ulonglong2 A1 = *(const ulonglong2*)&Ws[kk][64 + tx * 4];
            float4 s0 = *(const float4*)&Xs[kk][ty * 4];
            float4 s1 = *(const float4*)&Xs[kk][64 + ty * 4];
            unsigned long long aw[4] = {A0.x, A0.y, A1.x, A1.y};
            unsigned long long bs[8] = {dup2(s0.x), dup2(s0.y), dup2(s0.z), dup2(s0.w),
                                        dup2(s1.x), dup2(s1.y), dup2(s1.z), dup2(s1.w)};
#pragma unroll
            for (int si = 0; si < 8; si++)
#pragma unroll
                for (int cq = 0; cq < 4; cq++)
                    ffma2(acc[si][cq], aw[cq], bs[si]);
        }
        __syncthreads();
    }

    float4 bv0 = *(const float4*)(bv + cb + tx * 4);
    float4 bv1 = *(const float4*)(bv + cb + 64 + tx * 4);
    const unsigned char* mk = mask + (size_t)n * S_TOT;
#pragma unroll
    for (int si = 0; si < 8; si++) {
        int s = sb + ((si < 4) ? (ty * 4 + si) : (64 + ty * 4 + si - 4));
        if (s >= S_TOT) continue;
        bool m = mk[s] != 0;
        float4 r0, r1;
        r0.x = plo(acc[si][0]) + bv0.x;
        r0.y = phi(acc[si][0]) + bv0.y;
        r0.z = plo(acc[si][1]) + bv0.z;
        r0.w = phi(acc[si][1]) + bv0.w;
        r1.x = plo(acc[si][2]) + bv1.x;
        r1.y = phi(acc[si][2]) + bv1.y;
        r1.z = plo(acc[si][3]) + bv1.z;
        r1.w = phi(acc[si][3]) + bv1.w;
        if (m) { r0 = make_float4(0.f, 0.f, 0.f, 0.f); r1 = r0; }
        float* dst = g_value + (size_t)(n * S_TOT + s) * C_DIM + cb;
        *(float4*)(dst + tx * 4) = r0;
        *(float4*)(dst + 64 + tx * 4) = r1;
    }
}

// =====================================================================
// Kernel B: per level: [off;w] = [Wloc;Ww]@(x+pos)+bias, softmax(w),
//           bilinear-sample g_value, weighted sum -> g_pre[n][s][c]
// Block: 32 queries of one level, 256 threads (8 warps).
// =====================================================================
__global__ void __launch_bounds__(256) k_sample(
    const float* __restrict__ x, const float* __restrict__ pos,
    const unsigned char* __restrict__ mask,
    const float* __restrict__ vsz, const float* __restrict__ vsc,
    const float* __restrict__ Wloc, const float* __restrict__ bloc,
    const float* __restrict__ Ww, const float* __restrict__ bw)
{
    const int lvl = blockIdx.y, n = blockIdx.z;
    const int H = c_H[lvl], W = c_W[lvl];
    const int L = H * W, loff = c_off[lvl];
    const int q0 = blockIdx.x * 32;
    if (q0 >= L) return;

    __shared__ __align__(16) float Wl[16 * 100];  // [k][row], row-stride 100
    __shared__ __align__(16) float Xp[16][32];    // [k][q]
    __shared__ __align__(16) float P[96][32];     // rows 0..63: off, 64..95: w-logits

    const int t = threadIdx.x;
    const int tq = t & 31, rg = t >> 5;
    float acc[12];
#pragma unroll
    for (int j = 0; j < 12; j++) acc[j] = 0.0f;

    const size_t xbase = (size_t)n * C_DIM * S_TOT;
    for (int k0 = 0; k0 < C_DIM; k0 += 16) {
#pragma unroll
        for (int i = 0; i < 6; i++) {
            int u = t + i * 256;
            int r = u >> 4, kk = u & 15;
            float w = (r < 64) ? Wloc[(size_t)r * C_DIM + k0 + kk]
                               : Ww[(size_t)(r - 64) * C_DIM + k0 + kk];
            Wl[kk * 100 + r] = w;
        }
#pragma unroll
        for (int i = 0; i < 2; i++) {
            int u = t + i * 256;
            int kk = u >> 5, q = u & 31;
            int gq = q0 + q;
            float v = 0.0f;
            if (gq < L) {
                int s = loff + gq;
                if (!mask[(size_t)n * S_TOT + s]) {
                    size_t idx = xbase + (size_t)(k0 + kk) * S_TOT + s;
                    v = x[idx] + pos[idx];
                }
            }
            Xp[kk][q] = v;
        }
        __syncthreads();
#pragma unroll
        for (int kk = 0; kk < 16; kk++) {
            float xv = Xp[kk][tq];
            const float4* wr = (const float4*)&Wl[kk * 100 + rg * 12];
            float4 w0 = wr[0], w1 = wr[1], w2 = wr[2];
            acc[0] += w0.x * xv; acc[1]  += w0.y * xv; acc[2]  += w0.z * xv; acc[3]  += w0.w * xv;
            acc[4] += w1.x * xv; acc[5]  += w1.y * xv; acc[6]  += w1.z * xv; acc[7]  += w1.w * xv;
            acc[8] += w2.x * xv; acc[9]  += w2.y * xv; acc[10] += w2.z * xv; acc[11] += w2.w * xv;
        }
        __syncthreads();
    }
#pragma unroll
    for (int j = 0; j < 12; j++) {
        int r = rg * 12 + j;
        float b = (r < 64) ? bloc[r] : bw[r - 64];
        P[r][tq] = acc[j] + b;
    }
    __syncthreads();

    // ---- sampling epilogue: warp 'wid' handles queries {wid, wid+8, wid+16, wid+24} ----
    const int lane = t & 31, wid = t >> 5;
    const float scx = 2.0f * vsc[((size_t)n * FL_N + lvl) * 2 + 0] / vsz[((size_t)n * FL_N + lvl) * 2 + 0];
    const float scy = 2.0f * vsc[((size_t)n * FL_N + lvl) * 2 + 1] / vsz[((size_t)n * FL_N + lvl) * 2 + 1];

    for (int qq = wid; qq < 32; qq += 8) {
        int gq = q0 + qq;
        if (gq >= L) break;
        int row = gq / W, col = gq - row * W;
        float prex = col + 0.5f, prey = row + 0.5f;
        int s_q = loff + gq;
        float2* dstb = (float2*)(g_pre + (size_t)(n * S_TOT + s_q) * C_DIM);
#pragma unroll
        for (int m = 0; m < 8; m++) {
            // softmax over the 4 levels for this head/query
            float l0 = P[64 + m * 4 + 0][qq], l1 = P[64 + m * 4 + 1][qq];
            float l2 = P[64 + m * 4 + 2][qq], l3 = P[64 + m * 4 + 3][qq];
            float mx = fmaxf(fmaxf(l0, l1), fmaxf(l2, l3));
            float e0 = __expf(l0 - mx), e1 = __expf(l1 - mx);
            float e2 = __expf(l2 - mx), e3 = __expf(l3 - mx);
            float inv = 1.0f / (e0 + e1 + e2 + e3);
            float wgt[4] = {e0 * inv, e1 * inv, e2 * inv, e3 * inv};
            float a0 = 0.0f, a1 = 0.0f;
#pragma unroll
            for (int f = 0; f < 4; f++) {
                int Hf = c_H[f], Wf = c_W[f], lof = c_off[f];
                float offx = P[m * 8 + f * 2 + 0][qq];
                float offy = P[m * 8 + f * 2 + 1][qq];
                float xx = (offx + prex) * (scx * 0.5f * (float)Wf) - 0.5f;
                float yy = (offy + prey) * (scy * 0.5f * (float)Hf) - 0.5f;
                float x0f = floorf(xx), y0f = floorf(yy);
                int ix0 = (int)x0f, iy0 = (int)y0f;
                float wx1 = xx - x0f, wy1 = yy - y0f;
                float wx0 = 1.0f - wx1, wy0 = 1.0f - wy1;
                float wf = wgt[f];
                const float* vb = g_value + ((size_t)n * S_TOT + lof) * C_DIM + m * 64 + lane * 2;
#define CORNER(ix, iy, cw) \
                if ((unsigned)(ix) < (unsigned)Wf && (unsigned)(iy) < (unsigned)Hf) { \
                    float2 v = *(const float2*)(vb + ((size_t)(iy) * Wf + (ix)) * C_DIM); \
                    float w_ = wf * (cw); a0 += w_ * v.x; a1 += w_ * v.y; }
                CORNER(ix0,     iy0,     wx0 * wy0)
                CORNER(ix0 + 1, iy0,     wx1 * wy0)
                CORNER(ix0,     iy0 + 1, wx0 * wy1)
                CORNER(ix0 + 1, iy0 + 1, wx1 * wy1)
#undef CORNER
            }
            dstb[m * 32 + lane] = make_float2(a0, a1);
        }
    }
}

// =====================================================================
// Kernel C: out[n][c][s] = scale[c]*(sum_k Wo[c][k]*g_pre[n][s][k] + bo[c])
// 128(s) x 128(c) tile, f32x2 packed along s, coalesced float2 stores.
// =====================================================================
__global__ void __launch_bounds__(256) k_out(
    const float* __restrict__ Wo, const float* __restrict__ bo,
    const float* __restrict__ scale, float* __restrict__ out)
{
    __shared__ __align__(16) float Ws[16][128];   // [k][c]
    __shared__ __align__(16) float Xs[16][128];   // [k][s]
    const int sb = blockIdx.x * 128;
    const int cb = blockIdx.y * 128;
    const int n  = blockIdx.z;
    const int t  = threadIdx.x;
    const int tx = t & 15, ty = t >> 4;

    unsigned long long acc[8][4];
#pragma unroll
    for (int i = 0; i < 8; i++)
#pragma unroll
        for (int j = 0; j < 4; j++) acc[i][j] = 0ULL;

    for (int k0 = 0; k0 < C_DIM; k0 += 16) {
#pragma unroll
        for (int i = 0; i < 2; i++) {              // Wo tile -> [k][c]
            int u = t + i * 256;
            int cc = u >> 2, kq = u & 3;
            float4 w = *(const float4*)(Wo + (size_t)(cb + cc) * C_DIM + k0 + kq * 4);
            Ws[kq * 4 + 0][cc] = w.x;
            Ws[kq * 4 + 1][cc] = w.y;
            Ws[kq * 4 + 2][cc] = w.z;
            Ws[kq * 4 + 3][cc] = w.w;
        }
#pragma unroll
        for (int i = 0; i < 2; i++) {              // g_pre tile -> [k][s]
            int u = t + i * 256;
            int sq = u >> 2, kq = u & 3;
            int s = sb + sq;
            float4 v = make_float4(0.f, 0.f, 0.f, 0.f);
            if (s < S_TOT)
                v = *(const float4*)(g_pre + (size_t)(n * S_TOT + s) * C_DIM + k0 + kq * 4);
            Xs[kq * 4 + 0][sq] = v.x;
            Xs[kq * 4 + 1][sq] = v.y;
            Xs[kq * 4 + 2][sq] = v.z;
            Xs[kq * 4 + 3][sq] = v.w;
        }
        __syncthreads();
#pragma unroll
        for (int kk = 0; kk < 16; kk++) {
            ulonglong2 A0 = *(const ulonglong2*)&Xs[kk][tx * 4];
            ulonglong2 A1 = *(const ulonglong2*)&Xs[kk][64 + tx * 4];
            float4 c0 = *(const float4*)&Ws[kk][ty * 4];
            float4 c1 = *(const float4*)&Ws[kk][64 + ty * 4];
            unsigned long long as[4] = {A0.x, A0.y, A1.x, A1.y};
            unsigned long long bc[8] = {dup2(c0.x), dup2(c0.y), dup2(c0.z), dup2(c0.w),
                                        dup2(c1.x), dup2(c1.y), dup2(c1.z), dup2(c1.w)};
#pragma unroll
            for (int ci = 0; ci < 8; ci++)
#pragma unroll
                for (int j = 0; j < 4; j++)
                    ffma2(acc[ci][j], as[j], bc[ci]);
        }
        __syncthreads();
    }

#pragma unroll
    for (int ci = 0; ci < 8; ci++) {
        int c = cb + ((ci < 4) ? (ty * 4 + ci) : (64 + ty * 4 + ci - 4));
        float sc = scale[c], bb = bo[c];
        float* dst = out + (size_t)(n * C_DIM + c) * S_TOT;
#pragma unroll
        for (int j = 0; j < 4; j++) {
            int s = sb + ((j < 2) ? (tx * 4 + j * 2) : (64 + tx * 4 + (j - 2) * 2));
            float v0 = sc * (plo(acc[ci][j]) + bb);
            float v1 = sc * (phi(acc[ci][j]) + bb);
            if (s + 1 < S_TOT) {
                float2 p; p.x = v0; p.y = v1;
                *(float2*)(dst + s) = p;
            } else if (s < S_TOT) {
                dst[s] = v0;
            }
        }
    }
}

extern "C" void kernel_launch(void* const* d_in, const int* in_sizes, int n_in,
                              void* d_out, int out_size) {
    const float* x    = (const float*)d_in[0];
    const float* pos  = (const float*)d_in[1];
    const unsigned char* mask = (const unsigned char*)d_in[2];
    const float* vsz  = (const float*)d_in[3];
    const float* vsc  = (const float*)d_in[4];
    const float* Wv   = (const float*)d_in[5];
    const float* bv   = (const float*)d_in[6];
    const float* Wloc = (const float*)d_in[7];
    const float* bloc = (const float*)d_in[8];
    const float* Ww   = (const float*)d_in[9];
    const float* bw   = (const float*)d_in[10];
    const float* Wo   = (const float*)d_in[11];
    const float* bo   = (const float*)d_in[12];
    const float* scale = (const float*)d_in[13];
    float* out = (float*)d_out;

    dim3 gA((S_TOT + 127) / 128, 4, N_B);        // (104, 4, 2)
    k_value<<<gA, 256>>>(x, mask, Wv, bv);

    dim3 gB(313, 4, N_B);                        // 313 = ceil(10000/32), smaller levels early-exit
    k_sample<<<gB, 256>>>(x, pos, mask, vsz, vsc, Wloc, bloc, Ww, bw);

    dim3 gC((S_TOT + 127) / 128, 4, N_B);
    k_out<<<gC, 256>>>(Wo, bo, scale, out);
}

// round 9
// speedup vs baseline: 1.5873x; 1.5873x over previous
#include <cuda_runtime.h>
#include <cuda_bf16.h>
#include <math.h>

#define N_B    2
#define C_DIM  512
#define S_TOT  13294
#define FL_N   4

// Level geometry (H, W, flat offset in s)
__constant__ int c_H[4]   = {100, 50, 25, 13};
__constant__ int c_W[4]   = {100, 50, 25, 13};
__constant__ int c_off[4] = {0, 10000, 12500, 13125};

// ---------------- device scratch ----------------
__device__ __align__(16) float         g_value[N_B * S_TOT * C_DIM];   // fp32, (n,s,c)
__device__ __align__(16) __nv_bfloat16 g_xT_hi[N_B * S_TOT * C_DIM];   // x^T (n,s,k)
__device__ __align__(16) __nv_bfloat16 g_xT_lo[N_B * S_TOT * C_DIM];
__device__ __align__(16) __nv_bfloat16 g_pre_hi[N_B * S_TOT * C_DIM];  // sampled (n,s,c)
__device__ __align__(16) __nv_bfloat16 g_pre_lo[N_B * S_TOT * C_DIM];
__device__ __align__(16) __nv_bfloat16 g_Wv_hi[C_DIM * C_DIM];
__device__ __align__(16) __nv_bfloat16 g_Wv_lo[C_DIM * C_DIM];
__device__ __align__(16) __nv_bfloat16 g_Wo_hi[C_DIM * C_DIM];
__device__ __align__(16) __nv_bfloat16 g_Wo_lo[C_DIM * C_DIM];

// ---------------- PTX helpers (arch-generic, no 103a features) ----------------
__device__ __forceinline__ unsigned smem_u32(const void* p) {
    unsigned a;
    asm("{ .reg .u64 t; cvta.to.shared.u64 t, %1; cvt.u32.u64 %0, t; }" : "=r"(a) : "l"(p));
    return a;
}
__device__ __forceinline__ void cp16(unsigned dst, const void* src, int ok) {
    int sz = ok ? 16 : 0;
    asm volatile("cp.async.cg.shared.global [%0], [%1], 16, %2;"
                 :: "r"(dst), "l"(src), "r"(sz) : "memory");
}
#define CP_COMMIT() asm volatile("cp.async.commit_group;" ::: "memory")
#define CP_WAIT(n)  asm volatile("cp.async.wait_group %0;" :: "n"(n) : "memory")

#define LDSM4(r, addr) \
    asm volatile("ldmatrix.sync.aligned.m8n8.x4.shared.b16 {%0,%1,%2,%3}, [%4];" \
                 : "=r"((r)[0]), "=r"((r)[1]), "=r"((r)[2]), "=r"((r)[3]) : "r"(addr))

__device__ __forceinline__ void mma_bf16(float* d, const unsigned* a, const unsigned* b) {
    asm volatile(
        "mma.sync.aligned.m16n8k16.row.col.f32.bf16.bf16.f32 "
        "{%0,%1,%2,%3}, {%4,%5,%6,%7}, {%8,%9}, {%0,%1,%2,%3};"
        : "+f"(d[0]), "+f"(d[1]), "+f"(d[2]), "+f"(d[3])
        : "r"(a[0]), "r"(a[1]), "r"(a[2]), "r"(a[3]), "r"(b[0]), "r"(b[1]));
}

// smem geometry: padded rows (32 halves + 8 pad = 80 B) -> conflict-free ldmatrix
#define KC          32
#define ROW_B       80
#define BUF_B       (128 * ROW_B)      // 10240
#define STAGE_B     (4 * BUF_B)        // 40960  (Ah, Al, Bh, Bl)
#define GEMM_SMEM   (2 * STAGE_B)      // 81920
#define NCHUNK      (C_DIM / KC)       // 16

// =====================================================================
// prep: fp32 -> bf16 hi/lo elementwise (weights)
// =====================================================================
__global__ void k_split(const float* __restrict__ src,
                        __nv_bfloat16* __restrict__ hi, __nv_bfloat16* __restrict__ lo) {
    int i = blockIdx.x * 256 + threadIdx.x;
    float v = src[i];
    __nv_bfloat16 h = __float2bfloat16(v);
    hi[i] = h;
    lo[i] = __float2bfloat16(v - __bfloat162float(h));
}

// =====================================================================
// prep: x[n][k][s] fp32 -> xT_hi/lo[n][s][k] bf16 (32x32 smem transpose)
// =====================================================================
__global__ void k_convX(const float* __restrict__ x) {
    __shared__ float tile[32][33];
    const int s0 = blockIdx.x * 32, k0 = blockIdx.y * 32, n = blockIdx.z;
    const int tx = threadIdx.x, ty = threadIdx.y;
#pragma unroll
    for (int r = 0; r < 4; r++) {
        int k = k0 + ty + r * 8, s = s0 + tx;
        tile[ty + r * 8][tx] = (s < S_TOT) ? x[((size_t)n * C_DIM + k) * S_TOT + s] : 0.0f;
    }
    __syncthreads();
#pragma unroll
    for (int r = 0; r < 4; r++) {
        int s = s0 + ty + r * 8, k = k0 + tx;
        if (s < S_TOT) {
            float v = tile[tx][ty + r * 8];
            __nv_bfloat16 h = __float2bfloat16(v);
            size_t o = ((size_t)n * S_TOT + s) * C_DIM + k;
            g_xT_hi[o] = h;
            g_xT_lo[o] = __float2bfloat16(v - __bfloat162float(h));
        }
    }
}

// =====================================================================
// HMMA GEMM, bf16 2-term split (ah*bh + ah*bl + al*bh), fp32 reg acc.
// MODE 0: D[s][c] = xT @ Wv^T  -> g_value (+bv, mask)   A=xT(s), B=Wv(c)
// MODE 1: D[c][s] = Wo @ pre^T -> out (scale*(v+bo))    A=Wo(c), B=pre(s)
// Block 128(m) x 128(n), 8 warps of 32(m) x 64(n), K-chunk 32 double-buffered.
// =====================================================================
template<int MODE>
__global__ void __launch_bounds__(256, 2) k_gemm(
    const unsigned char* __restrict__ mask,
    const float* __restrict__ bias,
    const float* __restrict__ scl,
    float* __restrict__ outp)
{
    extern __shared__ char smem[];
    const int t = threadIdx.x, lane = t & 31, wid = t >> 5;
    const int mb = blockIdx.x * 128;
    const int nb = blockIdx.y * 128;
    const int n  = blockIdx.z;
    const unsigned sbase = smem_u32(smem);

    const __nv_bfloat16 *Ah, *Al, *Bh, *Bl;
    int a_lim, b_lim;
    if (MODE == 0) {
        Ah = g_xT_hi + (size_t)n * S_TOT * C_DIM;
        Al = g_xT_lo + (size_t)n * S_TOT * C_DIM;
        a_lim = S_TOT;
        Bh = g_Wv_hi; Bl = g_Wv_lo; b_lim = C_DIM;
    } else {
        Ah = g_Wo_hi; Al = g_Wo_lo; a_lim = C_DIM;
        Bh = g_pre_hi + (size_t)n * S_TOT * C_DIM;
        Bl = g_pre_lo + (size_t)n * S_TOT * C_DIM;
        b_lim = S_TOT;
    }

    // loader: thread t covers (row = u>>2, 16B-seg = u&3), u = t, t+256
    const int l_row0 = t >> 2, l_seg = t & 3;
#define ISSUE(chunk)                                                                   \
    {                                                                                  \
        const int k0 = (chunk) * KC;                                                   \
        const unsigned st_ = sbase + ((chunk) & 1) * STAGE_B;                          \
        _Pragma("unroll")                                                              \
        for (int i_ = 0; i_ < 2; i_++) {                                               \
            int row = l_row0 + i_ * 64;                                                \
            unsigned doff = row * ROW_B + l_seg * 16;                                  \
            int ra = mb + row; int oka = ra < a_lim; ra = oka ? ra : 0;                \
            size_t ga = (size_t)ra * C_DIM + k0 + l_seg * 8;                           \
            cp16(st_ + 0 * BUF_B + doff, Ah + ga, oka);                                \
            cp16(st_ + 1 * BUF_B + doff, Al + ga, oka);                                \
            int rb = nb + row; int okb = rb < b_lim; rb = okb ? rb : 0;                \
            size_t gb = (size_t)rb * C_DIM + k0 + l_seg * 8;                           \
            cp16(st_ + 2 * BUF_B + doff, Bh + gb, okb);                                \
            cp16(st_ + 3 * BUF_B + doff, Bl + gb, okb);                                \
        }                                                                              \
        CP_COMMIT();                                                                   \
    }

    const int wm = (wid >> 1) * 32;   // warp m-offset (4 rows of warps)
    const int wn = (wid & 1) * 64;    // warp n-offset (2 cols of warps)
    // ldmatrix per-thread offsets within a buffer
    const unsigned aoff = (wm + (lane & 15)) * ROW_B + ((lane & 16) ? 16 : 0);
    const unsigned boff = (wn + (lane & 7) + ((lane & 16) ? 8 : 0)) * ROW_B
                        + ((lane & 8) ? 16 : 0);

    float acc[2][8][4];
#pragma unroll
    for (int a = 0; a < 2; a++)
#pragma unroll
        for (int b = 0; b < 8; b++)
#pragma unroll
            for (int j = 0; j < 4; j++) acc[a][b][j] = 0.0f;

    ISSUE(0);
    for (int c = 0; c < NCHUNK; c++) {
        if (c + 1 < NCHUNK) { ISSUE(c + 1); CP_WAIT(1); }
        else                { CP_WAIT(0); }
        __syncthreads();
        const unsigned st = sbase + (c & 1) * STAGE_B;
#pragma unroll
        for (int ks = 0; ks < 2; ks++) {
            unsigned ahi[2][4], alo[2][4];
#pragma unroll
            for (int mt = 0; mt < 2; mt++) {
                LDSM4(ahi[mt], st + 0 * BUF_B + aoff + mt * (16 * ROW_B) + ks * 32);
                LDSM4(alo[mt], st + 1 * BUF_B + aoff + mt * (16 * ROW_B) + ks * 32);
            }
#pragma unroll
            for (int g = 0; g < 4; g++) {
                unsigned bh[4], bl[4];
                LDSM4(bh, st + 2 * BUF_B + boff + g * (16 * ROW_B) + ks * 32);
                LDSM4(bl, st + 3 * BUF_B + boff + g * (16 * ROW_B) + ks * 32);
#pragma unroll
                for (int j = 0; j < 2; j++) {
#pragma unroll
                    for (int mt = 0; mt < 2; mt++) {
                        float* d = acc[mt][g * 2 + j];
                        mma_bf16(d, ahi[mt], &bh[2 * j]);
                        mma_bf16(d, ahi[mt], &bl[2 * j]);
                        mma_bf16(d, alo[mt], &bh[2 * j]);
                    }
                }
            }
        }
        __syncthreads();
    }
#undef ISSUE

    // ---- epilogue: n-dim is the contiguous store dim in both modes ----
    if (MODE == 0) {
        const unsigned char* mk = mask + (size_t)n * S_TOT;
        float* dst = g_value + (size_t)n * S_TOT * C_DIM;
#pragma unroll
        for (int mt = 0; mt < 2; mt++) {
            int s0 = mb + wm + mt * 16 + (lane >> 2);
#pragma unroll
            for (int tn = 0; tn < 8; tn++) {
                int cc = nb + wn + tn * 8 + 2 * (lane & 3);
                float2 bp = *(const float2*)(bias + cc);
                float* d = acc[mt][tn];
                if (s0 < S_TOT) {
                    float m = mk[s0] ? 0.0f : 1.0f;
                    float2 v; v.x = m * (d[0] + bp.x); v.y = m * (d[1] + bp.y);
                    *(float2*)(dst + (size_t)s0 * C_DIM + cc) = v;
                }
                int s1 = s0 + 8;
                if (s1 < S_TOT) {
                    float m = mk[s1] ? 0.0f : 1.0f;
                    float2 v; v.x = m * (d[2] + bp.x); v.y = m * (d[3] + bp.y);
                    *(float2*)(dst + (size_t)s1 * C_DIM + cc) = v;
                }
            }
        }
    } else {
#pragma unroll
        for (int mt = 0; mt < 2; mt++) {
            int c0 = mb + wm + mt * 16 + (lane >> 2);
            int c1 = c0 + 8;
            float sc0 = scl[c0], b0 = bias[c0];
            float sc1 = scl[c1], b1 = bias[c1];
            float* r0 = outp + ((size_t)n * C_DIM + c0) * S_TOT;
            float* r1 = outp + ((size_t)n * C_DIM + c1) * S_TOT;
#pragma unroll
            for (int tn = 0; tn < 8; tn++) {
                int ss = nb + wn + tn * 8 + 2 * (lane & 3);
                float* d = acc[mt][tn];
                if (ss < S_TOT) {   // S_TOT even, ss even -> pair fully in-bounds
                    float2 v0; v0.x = sc0 * (d[0] + b0); v0.y = sc0 * (d[1] + b0);
                    *(float2*)(r0 + ss) = v0;
                    float2 v1; v1.x = sc1 * (d[2] + b1); v1.y = sc1 * (d[3] + b1);
                    *(float2*)(r1 + ss) = v1;
                }
            }
        }
    }
}

// =====================================================================
// k_sample: [off;w] = [Wloc;Ww]@(x+pos)+bias, softmax over levels,
// bilinear-sample g_value, weighted sum -> g_pre_hi/lo (bf16 split)
// =====================================================================
__global__ void __launch_bounds__(256) k_sample(
    const float* __restrict__ x, const float* __restrict__ pos,
    const unsigned char* __restrict__ mask,
    const float* __restrict__ vsz, const float* __restrict__ vsc,
    const float* __restrict__ Wloc, const float* __restrict__ bloc,
    const float* __restrict__ Ww, const float* __restrict__ bw)
{
    const int lvl = blockIdx.y, n = blockIdx.z;
    const int H = c_H[lvl], W = c_W[lvl];
    const int L = H * W, loff = c_off[lvl];
    const int q0 = blockIdx.x * 32;
    if (q0 >= L) return;

    __shared__ __align__(16) float Wl[16 * 100];
    __shared__ __align__(16) float Xp[16][32];
    __shared__ __align__(16) float P[96][32];

    const int t = threadIdx.x;
    const int tq = t & 31, rg = t >> 5;
    float acc[12];
#pragma unroll
    for (int j = 0; j < 12; j++) acc[j] = 0.0f;

    const size_t xbase = (size_t)n * C_DIM * S_TOT;
    for (int k0 = 0; k0 < C_DIM; k0 += 16) {
#pragma unroll
        for (int i = 0; i < 6; i++) {
            int u = t + i * 256;
            int r = u >> 4, kk = u & 15;
            float w = (r < 64) ? Wloc[(size_t)r * C_DIM + k0 + kk]
                               : Ww[(size_t)(r - 64) * C_DIM + k0 + kk];
            Wl[kk * 100 + r] = w;
        }
#pragma unroll
        for (int i = 0; i < 2; i++) {
            int u = t + i * 256;
            int kk = u >> 5, q = u & 31;
            int gq = q0 + q;
            float v = 0.0f;
            if (gq < L) {
                int s = loff + gq;
                if (!mask[(size_t)n * S_TOT + s]) {
                    size_t idx = xbase + (size_t)(k0 + kk) * S_TOT + s;
                    v = x[idx] + pos[idx];
                }
            }
            Xp[kk][q] = v;
        }
        __syncthreads();
#pragma unroll
        for (int kk = 0; kk < 16; kk++) {
            float xv = Xp[kk][tq];
            const float4* wr = (const float4*)&Wl[kk * 100 + rg * 12];
            float4 w0 = wr[0], w1 = wr[1], w2 = wr[2];
            acc[0] += w0.x * xv; acc[1]  += w0.y * xv; acc[2]  += w0.z * xv; acc[3]  += w0.w * xv;
            acc[4] += w1.x * xv; acc[5]  += w1.y * xv; acc[6]  += w1.z * xv; acc[7]  += w1.w * xv;
            acc[8] += w2.x * xv; acc[9]  += w2.y * xv; acc[10] += w2.z * xv; acc[11] += w2.w * xv;
        }
        __syncthreads();
    }
#pragma unroll
    for (int j = 0; j < 12; j++) {
        int r = rg * 12 + j;
        float b = (r < 64) ? bloc[r] : bw[r - 64];
        P[r][tq] = acc[j] + b;
    }
    __syncthreads();

    const int lane = t & 31, wid = t >> 5;
    const float scx = 2.0f * vsc[((size_t)n * FL_N + lvl) * 2 + 0] / vsz[((size_t)n * FL_N + lvl) * 2 + 0];
    const float scy = 2.0f * vsc[((size_t)n * FL_N + lvl) * 2 + 1] / vsz[((size_t)n * FL_N + lvl) * 2 + 1];

    for (int qq = wid; qq < 32; qq += 8) {
        int gq = q0 + qq;
        if (gq >= L) break;
        int row = gq / W, col = gq - row * W;
        float prex = col + 0.5f, prey = row + 0.5f;
        int s_q = loff + gq;
#pragma unroll
        for (int m = 0; m < 8; m++) {
            float l0 = P[64 + m * 4 + 0][qq], l1 = P[64 + m * 4 + 1][qq];
            float l2 = P[64 + m * 4 + 2][qq], l3 = P[64 + m * 4 + 3][qq];
            float mx = fmaxf(fmaxf(l0, l1), fmaxf(l2, l3));
            float e0 = __expf(l0 - mx), e1 = __expf(l1 - mx);
            float e2 = __expf(l2 - mx), e3 = __expf(l3 - mx);
            float inv = 1.0f / (e0 + e1 + e2 + e3);
            float wgt[4] = {e0 * inv, e1 * inv, e2 * inv, e3 * inv};
            float a0 = 0.0f, a1 = 0.0f;
#pragma unroll
            for (int f = 0; f < 4; f++) {
                int Hf = c_H[f], Wf = c_W[f], lof = c_off[f];
                float offx = P[m * 8 + f * 2 + 0][qq];
                float offy = P[m * 8 + f * 2 + 1][qq];
                float xx = (offx + prex) * (scx * 0.5f * (float)Wf) - 0.5f;
                float yy = (offy + prey) * (scy * 0.5f * (float)Hf) - 0.5f;
                float x0f = floorf(xx), y0f = floorf(yy);
                int ix0 = (int)x0f, iy0 = (int)y0f;
                float wx1 = xx - x0f, wy1 = yy - y0f;
                float wx0 = 1.0f - wx1, wy0 = 1.0f - wy1;
                float wf = wgt[f];
                const float* vb = g_value + ((size_t)n * S_TOT + lof) * C_DIM + m * 64 + lane * 2;
#define CORNER(ix, iy, cw) \
                if ((unsigned)(ix) < (unsigned)Wf && (unsigned)(iy) < (unsigned)Hf) { \
                    float2 v = *(const float2*)(vb + ((size_t)(iy) * Wf + (ix)) * C_DIM); \
                    float w_ = wf * (cw); a0 += w_ * v.x; a1 += w_ * v.y; }
                CORNER(ix0,     iy0,     wx0 * wy0)
                CORNER(ix0 + 1, iy0,     wx1 * wy0)
                CORNER(ix0,     iy0 + 1, wx0 * wy1)
                CORNER(ix0 + 1, iy0 + 1, wx1 * wy1)
#undef CORNER
            }
            __nv_bfloat162 hv, lv;
            hv.x = __float2bfloat16(a0);
            lv.x = __float2bfloat16(a0 - __bfloat162float(hv.x));
            hv.y = __float2bfloat16(a1);
            lv.y = __float2bfloat16(a1 - __bfloat162float(hv.y));
            size_t oi = (size_t)(n * S_TOT + s_q) * (C_DIM / 2) + m * 32 + lane;
            ((__nv_bfloat162*)g_pre_hi)[oi] = hv;
            ((__nv_bfloat162*)g_pre_lo)[oi] = lv;
        }
    }
}

extern "C" void kernel_launch(void* const* d_in, const int* in_sizes, int n_in,
                              void* d_out, int out_size) {
    const float* x    = (const float*)d_in[0];
    const float* pos  = (const float*)d_in[1];
    const unsigned char* mask = (const unsigned char*)d_in[2];
    const float* vsz  = (const float*)d_in[3];
    const float* vsc  = (const float*)d_in[4];
    const float* Wv   = (const float*)d_in[5];
    const float* bv   = (const float*)d_in[6];
    const float* Wloc = (const float*)d_in[7];
    const float* bloc = (const float*)d_in[8];
    const float* Ww   = (const float*)d_in[9];
    const float* bw   = (const float*)d_in[10];
    const float* Wo   = (const float*)d_in[11];
    const float* bo   = (const float*)d_in[12];
    const float* scale = (const float*)d_in[13];
    float* out = (float*)d_out;

    cudaFuncSetAttribute(k_gemm<0>, cudaFuncAttributeMaxDynamicSharedMemorySize, GEMM_SMEM);
    cudaFuncSetAttribute(k_gemm<1>, cudaFuncAttributeMaxDynamicSharedMemorySize, GEMM_SMEM);

    void *p_wvh, *p_wvl, *p_woh, *p_wol;
    cudaGetSymbolAddress(&p_wvh, g_Wv_hi);
    cudaGetSymbolAddress(&p_wvl, g_Wv_lo);
    cudaGetSymbolAddress(&p_woh, g_Wo_hi);
    cudaGetSymbolAddress(&p_wol, g_Wo_lo);

    // prep: split weights, transpose+split x
    k_split<<<1024, 256>>>(Wv, (__nv_bfloat16*)p_wvh, (__nv_bfloat16*)p_wvl);
    k_split<<<1024, 256>>>(Wo, (__nv_bfloat16*)p_woh, (__nv_bfloat16*)p_wol);
    k_convX<<<dim3((S_TOT + 31) / 32, C_DIM / 32, N_B), dim3(32, 8)>>>(x);

    // value GEMM: D[s][c], m = s, n = c
    k_gemm<0><<<dim3((S_TOT + 127) / 128, C_DIM / 128, N_B), 256, GEMM_SMEM>>>(
        mask, bv, nullptr, nullptr);

    // deformable sampling
    k_sample<<<dim3(313, FL_N, N_B), 256>>>(x, pos, mask, vsz, vsc, Wloc, bloc, Ww, bw);

    // output GEMM: D[c][s], m = c, n = s
    k_gemm<1><<<dim3(C_DIM / 128, (S_TOT + 127) / 128, N_B), 256, GEMM_SMEM>>>(
        mask, bo, scale, out);
}

// round 10
// speedup vs baseline: 1.8787x; 1.1836x over previous
#include <cuda_runtime.h>
#include <cuda_bf16.h>
#include <math.h>

#define N_B    2
#define C_DIM  512
#define S_TOT  13294
#define FL_N   4

// Level geometry (H, W, flat offset in s)
__constant__ int c_H[4]   = {100, 50, 25, 13};
__constant__ int c_W[4]   = {100, 50, 25, 13};
__constant__ int c_off[4] = {0, 10000, 12500, 13125};

// ---------------- device scratch ----------------
__device__ __align__(16) float         g_value[N_B * S_TOT * C_DIM];   // fp32, (n,s,c)
__device__ __align__(16) float         g_offw[N_B * S_TOT * 128];      // fp32 logits per query
__device__ __align__(16) __nv_bfloat16 g_xT_hi[N_B * S_TOT * C_DIM];   // x^T (n,s,k)
__device__ __align__(16) __nv_bfloat16 g_xT_lo[N_B * S_TOT * C_DIM];
__device__ __align__(16) __nv_bfloat16 g_xpT_hi[N_B * S_TOT * C_DIM];  // (x+pos)^T
__device__ __align__(16) __nv_bfloat16 g_xpT_lo[N_B * S_TOT * C_DIM];
__device__ __align__(16) __nv_bfloat16 g_pre_hi[N_B * S_TOT * C_DIM];  // sampled (n,s,c)
__device__ __align__(16) __nv_bfloat16 g_pre_lo[N_B * S_TOT * C_DIM];
__device__ __align__(16) __nv_bfloat16 g_Wv_hi[C_DIM * C_DIM];
__device__ __align__(16) __nv_bfloat16 g_Wv_lo[C_DIM * C_DIM];
__device__ __align__(16) __nv_bfloat16 g_Wo_hi[C_DIM * C_DIM];
__device__ __align__(16) __nv_bfloat16 g_Wo_lo[C_DIM * C_DIM];
__device__ __align__(16) __nv_bfloat16 g_Wc_hi[128 * C_DIM];           // [Wloc;Ww;0] padded
__device__ __align__(16) __nv_bfloat16 g_Wc_lo[128 * C_DIM];
__device__ __align__(16) float         g_bcat[128];                    // [bloc;bw;0]

// ---------------- PTX helpers (arch-generic, no 103a features) ----------------
__device__ __forceinline__ unsigned smem_u32(const void* p) {
    unsigned a;
    asm("{ .reg .u64 t; cvta.to.shared.u64 t, %1; cvt.u32.u64 %0, t; }" : "=r"(a) : "l"(p));
    return a;
}
__device__ __forceinline__ void cp16(unsigned dst, const void* src, int ok) {
    int sz = ok ? 16 : 0;
    asm volatile("cp.async.cg.shared.global [%0], [%1], 16, %2;"
                 :: "r"(dst), "l"(src), "r"(sz) : "memory");
}
#define CP_COMMIT() asm volatile("cp.async.commit_group;" ::: "memory")
#define CP_WAIT(n)  asm volatile("cp.async.wait_group %0;" :: "n"(n) : "memory")

#define LDSM4(r, addr) \
    asm volatile("ldmatrix.sync.aligned.m8n8.x4.shared.b16 {%0,%1,%2,%3}, [%4];" \
                 : "=r"((r)[0]), "=r"((r)[1]), "=r"((r)[2]), "=r"((r)[3]) : "r"(addr))

__device__ __forceinline__ void mma_bf16(float* d, const unsigned* a, const unsigned* b) {
    asm volatile(
        "mma.sync.aligned.m16n8k16.row.col.f32.bf16.bf16.f32 "
        "{%0,%1,%2,%3}, {%4,%5,%6,%7}, {%8,%9}, {%0,%1,%2,%3};"
        : "+f"(d[0]), "+f"(d[1]), "+f"(d[2]), "+f"(d[3])
        : "r"(a[0]), "r"(a[1]), "r"(a[2]), "r"(a[3]), "r"(b[0]), "r"(b[1]));
}

// smem geometry: padded rows (32 halves + 8 pad = 80 B) -> conflict-free ldmatrix
#define KC          32
#define ROW_B       80
#define BUF_B       (128 * ROW_B)      // 10240
#define STAGE_B     (4 * BUF_B)        // 40960  (Ah, Al, Bh, Bl)
#define GEMM_SMEM   (2 * STAGE_B)      // 81920
#define NCHUNK      (C_DIM / KC)       // 16

// =====================================================================
// prep: fp32 -> bf16 hi/lo elementwise (weights)
// =====================================================================
__global__ void k_split(const float* __restrict__ src,
                        __nv_bfloat16* __restrict__ hi, __nv_bfloat16* __restrict__ lo) {
    int i = blockIdx.x * 256 + threadIdx.x;
    float v = src[i];
    __nv_bfloat16 h = __float2bfloat16(v);
    hi[i] = h;
    lo[i] = __float2bfloat16(v - __bfloat162float(h));
}

// =====================================================================
// prep: [Wloc(64);Ww(32);0(32)] -> g_Wc hi/lo (128x512), g_bcat
// =====================================================================
__global__ void k_prep_w(const float* __restrict__ Wloc, const float* __restrict__ bloc,
                         const float* __restrict__ Ww,   const float* __restrict__ bw) {
    int r = blockIdx.x, c = threadIdx.x;
    float v = (r < 64) ? Wloc[(size_t)r * C_DIM + c]
            : (r < 96) ? Ww[(size_t)(r - 64) * C_DIM + c] : 0.0f;
    __nv_bfloat16 h = __float2bfloat16(v);
    g_Wc_hi[(size_t)r * C_DIM + c] = h;
    g_Wc_lo[(size_t)r * C_DIM + c] = __float2bfloat16(v - __bfloat162float(h));
    if (c == 0)
        g_bcat[r] = (r < 64) ? bloc[r] : (r < 96) ? bw[r - 64] : 0.0f;
}

// =====================================================================
// prep: x,pos [n][k][s] fp32 -> xT and (x+pos)T hi/lo bf16 (32x32 transpose)
// =====================================================================
__global__ void k_convX(const float* __restrict__ x, const float* __restrict__ pos,
                        const unsigned char* __restrict__ mask) {
    __shared__ float tx[32][33], tp[32][33];
    const int s0 = blockIdx.x * 32, k0 = blockIdx.y * 32, n = blockIdx.z;
    const int txi = threadIdx.x, tyi = threadIdx.y;
#pragma unroll
    for (int r = 0; r < 4; r++) {
        int k = k0 + tyi + r * 8, s = s0 + txi;
        size_t gi = ((size_t)n * C_DIM + k) * S_TOT + s;
        tx[tyi + r * 8][txi] = (s < S_TOT) ? x[gi] : 0.0f;
        tp[tyi + r * 8][txi] = (s < S_TOT) ? pos[gi] : 0.0f;
    }
    __syncthreads();
#pragma unroll
    for (int r = 0; r < 4; r++) {
        int s = s0 + tyi + r * 8, k = k0 + txi;
        if (s < S_TOT) {
            float xv = tx[txi][tyi + r * 8];
            float pv = tp[txi][tyi + r * 8];
            bool m = mask[(size_t)n * S_TOT + s] != 0;
            size_t o = ((size_t)n * S_TOT + s) * C_DIM + k;
            __nv_bfloat16 h = __float2bfloat16(xv);
            g_xT_hi[o] = h;
            g_xT_lo[o] = __float2bfloat16(xv - __bfloat162float(h));
            float xp = m ? 0.0f : (xv + pv);
            __nv_bfloat16 hp = __float2bfloat16(xp);
            g_xpT_hi[o] = hp;
            g_xpT_lo[o] = __float2bfloat16(xp - __bfloat162float(hp));
        }
    }
}

// =====================================================================
// HMMA GEMM, bf16 2-term split (ah*bh + ah*bl + al*bh), fp32 reg acc.
// MODE 0: D[s][c] = xT @ Wv^T   -> g_value (+bv, mask)   A=xT(s),  B=Wv(c)
// MODE 1: D[c][s] = Wo @ pre^T  -> out (scale*(v+bo))    A=Wo(c),  B=pre(s)
// MODE 2: D[s][r] = xpT @ Wc^T  -> g_offw (+bcat)        A=xpT(s), B=Wc(r,128)
// Block 128(m) x 128(n), 8 warps of 32(m) x 64(n), K-chunk 32 double-buffered.
// =====================================================================
template<int MODE>
__global__ void __launch_bounds__(256, 2) k_gemm(
    const unsigned char* __restrict__ mask,
    const float* __restrict__ bias,
    const float* __restrict__ scl,
    float* __restrict__ outp)
{
    extern __shared__ char smem[];
    const int t = threadIdx.x, lane = t & 31, wid = t >> 5;
    const int mb = blockIdx.x * 128;
    const int nb = blockIdx.y * 128;
    const int n  = blockIdx.z;
    const unsigned sbase = smem_u32(smem);

    const __nv_bfloat16 *Ah, *Al, *Bh, *Bl;
    int a_lim, b_lim;
    if (MODE == 0) {
        Ah = g_xT_hi + (size_t)n * S_TOT * C_DIM;
        Al = g_xT_lo + (size_t)n * S_TOT * C_DIM;
        a_lim = S_TOT;
        Bh = g_Wv_hi; Bl = g_Wv_lo; b_lim = C_DIM;
    } else if (MODE == 1) {
        Ah = g_Wo_hi; Al = g_Wo_lo; a_lim = C_DIM;
        Bh = g_pre_hi + (size_t)n * S_TOT * C_DIM;
        Bl = g_pre_lo + (size_t)n * S_TOT * C_DIM;
        b_lim = S_TOT;
    } else {
        Ah = g_xpT_hi + (size_t)n * S_TOT * C_DIM;
        Al = g_xpT_lo + (size_t)n * S_TOT * C_DIM;
        a_lim = S_TOT;
        Bh = g_Wc_hi; Bl = g_Wc_lo; b_lim = 128;
    }

    const int l_row0 = t >> 2, l_seg = t & 3;
#define ISSUE(chunk)                                                                   \
    {                                                                                  \
        const int k0 = (chunk) * KC;                                                   \
        const unsigned st_ = sbase + ((chunk) & 1) * STAGE_B;                          \
        _Pragma("unroll")                                                              \
        for (int i_ = 0; i_ < 2; i_++) {                                               \
            int row = l_row0 + i_ * 64;                                                \
            unsigned doff = row * ROW_B + l_seg * 16;                                  \
            int ra = mb + row; int oka = ra < a_lim; ra = oka ? ra : 0;                \
            size_t ga = (size_t)ra * C_DIM + k0 + l_seg * 8;                           \
            cp16(st_ + 0 * BUF_B + doff, Ah + ga, oka);                                \
            cp16(st_ + 1 * BUF_B + doff, Al + ga, oka);                                \
            int rb = nb + row; int okb = rb < b_lim; rb = okb ? rb : 0;                \
            size_t gb = (size_t)rb * C_DIM + k0 + l_seg * 8;                           \
            cp16(st_ + 2 * BUF_B + doff, Bh + gb, okb);                                \
            cp16(st_ + 3 * BUF_B + doff, Bl + gb, okb);                                \
        }                                                                              \
        CP_COMMIT();                                                                   \
    }

    const int wm = (wid >> 1) * 32;
    const int wn = (wid & 1) * 64;
    const unsigned aoff = (wm + (lane & 15)) * ROW_B + ((lane & 16) ? 16 : 0);
    const unsigned boff = (wn + (lane & 7) + ((lane & 16) ? 8 : 0)) * ROW_B
                        + ((lane & 8) ? 16 : 0);

    float acc[2][8][4];
#pragma unroll
    for (int a = 0; a < 2; a++)
#pragma unroll
        for (int b = 0; b < 8; b++)
#pragma unroll
            for (int j = 0; j < 4; j++) acc[a][b][j] = 0.0f;

    ISSUE(0);
    for (int c = 0; c < NCHUNK; c++) {
        if (c + 1 < NCHUNK) { ISSUE(c + 1); CP_WAIT(1); }
        else                { CP_WAIT(0); }
        __syncthreads();
        const unsigned st = sbase + (c & 1) * STAGE_B;
#pragma unroll
        for (int ks = 0; ks < 2; ks++) {
            unsigned ahi[2][4], alo[2][4];
#pragma unroll
            for (int mt = 0; mt < 2; mt++) {
                LDSM4(ahi[mt], st + 0 * BUF_B + aoff + mt * (16 * ROW_B) + ks * 32);
                LDSM4(alo[mt], st + 1 * BUF_B + aoff + mt * (16 * ROW_B) + ks * 32);
            }
#pragma unroll
            for (int g = 0; g < 4; g++) {
                unsigned bh[4], bl[4];
                LDSM4(bh, st + 2 * BUF_B + boff + g * (16 * ROW_B) + ks * 32);
                LDSM4(bl, st + 3 * BUF_B + boff + g * (16 * ROW_B) + ks * 32);
#pragma unroll
                for (int j = 0; j < 2; j++) {
#pragma unroll
                    for (int mt = 0; mt < 2; mt++) {
                        float* d = acc[mt][g * 2 + j];
                        mma_bf16(d, ahi[mt], &bh[2 * j]);
                        mma_bf16(d, ahi[mt], &bl[2 * j]);
                        mma_bf16(d, alo[mt], &bh[2 * j]);
                    }
                }
            }
        }
        __syncthreads();
    }
#undef ISSUE

    // ---- epilogue: n-dim is the contiguous store dim in all modes ----
    if (MODE == 0) {
        const unsigned char* mk = mask + (size_t)n * S_TOT;
        float* dst = g_value + (size_t)n * S_TOT * C_DIM;
#pragma unroll
        for (int mt = 0; mt < 2; mt++) {
            int s0 = mb + wm + mt * 16 + (lane >> 2);
#pragma unroll
            for (int tn = 0; tn < 8; tn++) {
                int cc = nb + wn + tn * 8 + 2 * (lane & 3);
                float2 bp = *(const float2*)(bias + cc);
                float* d = acc[mt][tn];
                if (s0 < S_TOT) {
                    float m = mk[s0] ? 0.0f : 1.0f;
                    float2 v; v.x = m * (d[0] + bp.x); v.y = m * (d[1] + bp.y);
                    *(float2*)(dst + (size_t)s0 * C_DIM + cc) = v;
                }
                int s1 = s0 + 8;
                if (s1 < S_TOT) {
                    float m = mk[s1] ? 0.0f : 1.0f;
                    float2 v; v.x = m * (d[2] + bp.x); v.y = m * (d[3] + bp.y);
                    *(float2*)(dst + (size_t)s1 * C_DIM + cc) = v;
                }
            }
        }
    } else if (MODE == 1) {
#pragma unroll
        for (int mt = 0; mt < 2; mt++) {
            int c0 = mb + wm + mt * 16 + (lane >> 2);
            int c1 = c0 + 8;
            float sc0 = scl[c0], b0 = bias[c0];
            float sc1 = scl[c1], b1 = bias[c1];
            float* r0 = outp + ((size_t)n * C_DIM + c0) * S_TOT;
            float* r1 = outp + ((size_t)n * C_DIM + c1) * S_TOT;
#pragma unroll
            for (int tn = 0; tn < 8; tn++) {
                int ss = nb + wn + tn * 8 + 2 * (lane & 3);
                float* d = acc[mt][tn];
                if (ss < S_TOT) {
                    float2 v0; v0.x = sc0 * (d[0] + b0); v0.y = sc0 * (d[1] + b0);
                    *(float2*)(r0 + ss) = v0;
                    float2 v1; v1.x = sc1 * (d[2] + b1); v1.y = sc1 * (d[3] + b1);
                    *(float2*)(r1 + ss) = v1;
                }
            }
        }
    } else {
        float* dst = g_offw + (size_t)n * S_TOT * 128;
#pragma unroll
        for (int mt = 0; mt < 2; mt++) {
            int s0 = mb + wm + mt * 16 + (lane >> 2);
#pragma unroll
            for (int tn = 0; tn < 8; tn++) {
                int cc = wn + tn * 8 + 2 * (lane & 3);
                float2 bp = *(const float2*)(bias + cc);
                float* d = acc[mt][tn];
                if (s0 < S_TOT) {
                    float2 v; v.x = d[0] + bp.x; v.y = d[1] + bp.y;
                    *(float2*)(dst + (size_t)s0 * 128 + cc) = v;
                }
                int s1 = s0 + 8;
                if (s1 < S_TOT) {
                    float2 v; v.x = d[2] + bp.x; v.y = d[3] + bp.y;
                    *(float2*)(dst + (size_t)s1 * 128 + cc) = v;
                }
            }
        }
    }
}

// =====================================================================
// k_gather: read logits from g_offw, softmax over levels, bilinear-sample
// g_value, weighted sum -> g_pre_hi/lo. One warp per query, 8 warps/block.
// =====================================================================
__global__ void __launch_bounds__(256) k_gather(
    const float* __restrict__ vsz, const float* __restrict__ vsc)
{
    const int lvl = blockIdx.y, n = blockIdx.z;
    const int H = c_H[lvl], W = c_W[lvl];
    const int L = H * W, loff = c_off[lvl];
    const int wid = threadIdx.x >> 5, lane = threadIdx.x & 31;
    const int gq = blockIdx.x * 8 + wid;
    if (gq >= L) return;

    const float scx = 2.0f * vsc[((size_t)n * FL_N + lvl) * 2 + 0] / vsz[((size_t)n * FL_N + lvl) * 2 + 0];
    const float scy = 2.0f * vsc[((size_t)n * FL_N + lvl) * 2 + 1] / vsz[((size_t)n * FL_N + lvl) * 2 + 1];

    int row = gq / W, col = gq - row * W;
    float prex = col + 0.5f, prey = row + 0.5f;
    int s_q = loff + gq;

    const float* ow = g_offw + (size_t)(n * S_TOT + s_q) * 128;
    float v0 = ow[lane], v1 = ow[32 + lane], v2 = ow[64 + lane];

    for (int m = 0; m < 8; m++) {
        float vo = (m < 4) ? v0 : v1;
        // softmax over 4 levels (w-logit rows 64+m*4+f -> v2 lane m*4+f)
        float l0 = __shfl_sync(0xFFFFFFFFu, v2, m * 4 + 0);
        float l1 = __shfl_sync(0xFFFFFFFFu, v2, m * 4 + 1);
        float l2 = __shfl_sync(0xFFFFFFFFu, v2, m * 4 + 2);
        float l3 = __shfl_sync(0xFFFFFFFFu, v2, m * 4 + 3);
        float mx = fmaxf(fmaxf(l0, l1), fmaxf(l2, l3));
        float e0 = __expf(l0 - mx), e1 = __expf(l1 - mx);
        float e2 = __expf(l2 - mx), e3 = __expf(l3 - mx);
        float inv = 1.0f / (e0 + e1 + e2 + e3);
        float wgt[4] = {e0 * inv, e1 * inv, e2 * inv, e3 * inv};

        float a0 = 0.0f, a1 = 0.0f;
#pragma unroll
        for (int f = 0; f < 4; f++) {
            int Hf = c_H[f], Wf = c_W[f], lof = c_off[f];
            int rbase = (m * 8 + f * 2) & 31;
            float offx = __shfl_sync(0xFFFFFFFFu, vo, rbase);
            float offy = __shfl_sync(0xFFFFFFFFu, vo, rbase + 1);
            float xx = (offx + prex) * (scx * 0.5f * (float)Wf) - 0.5f;
            float yy = (offy + prey) * (scy * 0.5f * (float)Hf) - 0.5f;
            float x0f = floorf(xx), y0f = floorf(yy);
            int ix0 = (int)x0f, iy0 = (int)y0f;
            float wx1 = xx - x0f, wy1 = yy - y0f;
            float wx0 = 1.0f - wx1, wy0 = 1.0f - wy1;
            float wf = wgt[f];
            const float* vb = g_value + ((size_t)n * S_TOT + lof) * C_DIM + m * 64 + lane * 2;
#define CORNER(ix, iy, cw) \
            if ((unsigned)(ix) < (unsigned)Wf && (unsigned)(iy) < (unsigned)Hf) { \
                float2 v = *(const float2*)(vb + ((size_t)(iy) * Wf + (ix)) * C_DIM); \
                float w_ = wf * (cw); a0 += w_ * v.x; a1 += w_ * v.y; }
            CORNER(ix0,     iy0,     wx0 * wy0)
            CORNER(ix0 + 1, iy0,     wx1 * wy0)
            CORNER(ix0,     iy0 + 1, wx0 * wy1)
            CORNER(ix0 + 1, iy0 + 1, wx1 * wy1)
#undef CORNER
        }
        __nv_bfloat162 hv, lv;
        hv.x = __float2bfloat16(a0);
        lv.x = __float2bfloat16(a0 - __bfloat162float(hv.x));
        hv.y = __float2bfloat16(a1);
        lv.y = __float2bfloat16(a1 - __bfloat162float(hv.y));
        size_t oi = (size_t)(n * S_TOT + s_q) * (C_DIM / 2) + m * 32 + lane;
        ((__nv_bfloat162*)g_pre_hi)[oi] = hv;
        ((__nv_bfloat162*)g_pre_lo)[oi] = lv;
    }
}

extern "C" void kernel_launch(void* const* d_in, const int* in_sizes, int n_in,
                              void* d_out, int out_size) {
    const float* x    = (const float*)d_in[0];
    const float* pos  = (const float*)d_in[1];
    const unsigned char* mask = (const unsigned char*)d_in[2];
    const float* vsz  = (const float*)d_in[3];
    const float* vsc  = (const float*)d_in[4];
    const float* Wv   = (const float*)d_in[5];
    const float* bv   = (const float*)d_in[6];
    const float* Wloc = (const float*)d_in[7];
    const float* bloc = (const float*)d_in[8];
    const float* Ww   = (const float*)d_in[9];
    const float* bw   = (const float*)d_in[10];
    const float* Wo   = (const float*)d_in[11];
    const float* bo   = (const float*)d_in[12];
    const float* scale = (const float*)d_in[13];
    float* out = (float*)d_out;

    cudaFuncSetAttribute(k_gemm<0>, cudaFuncAttributeMaxDynamicSharedMemorySize, GEMM_SMEM);
    cudaFuncSetAttribute(k_gemm<1>, cudaFuncAttributeMaxDynamicSharedMemorySize, GEMM_SMEM);
    cudaFuncSetAttribute(k_gemm<2>, cudaFuncAttributeMaxDynamicSharedMemorySize, GEMM_SMEM);

    void *p_wvh, *p_wvl, *p_woh, *p_wol, *p_bcat;
    cudaGetSymbolAddress(&p_wvh, g_Wv_hi);
    cudaGetSymbolAddress(&p_wvl, g_Wv_lo);
    cudaGetSymbolAddress(&p_woh, g_Wo_hi);
    cudaGetSymbolAddress(&p_wol, g_Wo_lo);
    cudaGetSymbolAddress(&p_bcat, g_bcat);

    // prep: split weights, build concat proj weights, transpose+split x / x+pos
    k_split<<<1024, 256>>>(Wv, (__nv_bfloat16*)p_wvh, (__nv_bfloat16*)p_wvl);
    k_split<<<1024, 256>>>(Wo, (__nv_bfloat16*)p_woh, (__nv_bfloat16*)p_wol);
    k_prep_w<<<128, 512>>>(Wloc, bloc, Ww, bw);
    k_convX<<<dim3((S_TOT + 31) / 32, C_DIM / 32, N_B), dim3(32, 8)>>>(x, pos, mask);

    // value GEMM: D[s][c]
    k_gemm<0><<<dim3((S_TOT + 127) / 128, C_DIM / 128, N_B), 256, GEMM_SMEM>>>(
        mask, bv, nullptr, nullptr);

    // offset/weight logits GEMM: D[s][r], N = 128
    k_gemm<2><<<dim3((S_TOT + 127) / 128, 1, N_B), 256, GEMM_SMEM>>>(
        mask, (const float*)p_bcat, nullptr, nullptr);

    // deformable sampling (gather-only)
    k_gather<<<dim3(1250, FL_N, N_B), 256>>>(vsz, vsc);

    // output GEMM: D[c][s]
    k_gemm<1><<<dim3(C_DIM / 128, (S_TOT + 127) / 128, N_B), 256, GEMM_SMEM>>>(
        mask, bo, scale, out);
}

// round 12
// speedup vs baseline: 1.9314x; 1.0281x over previous
#include <cuda_runtime.h>
#include <cuda_bf16.h>
#include <math.h>

#define N_B    2
#define C_DIM  512
#define S_TOT  13294
#define FL_N   4

// Level geometry (H, W, flat offset in s)
__constant__ int c_H[4]   = {100, 50, 25, 13};
__constant__ int c_W[4]   = {100, 50, 25, 13};
__constant__ int c_off[4] = {0, 10000, 12500, 13125};

// ---------------- device scratch ----------------
__device__ __align__(16) float         g_value[N_B * S_TOT * C_DIM];   // fp32, (n,s,c)
__device__ __align__(16) float         g_offw[N_B * S_TOT * 128];      // fp32 logits per query
__device__ __align__(16) __nv_bfloat16 g_xT_hi[N_B * S_TOT * C_DIM];   // x^T (n,s,k)
__device__ __align__(16) __nv_bfloat16 g_xT_lo[N_B * S_TOT * C_DIM];
__device__ __align__(16) __nv_bfloat16 g_xpT_hi[N_B * S_TOT * C_DIM];  // (x+pos)^T
__device__ __align__(16) __nv_bfloat16 g_xpT_lo[N_B * S_TOT * C_DIM];
__device__ __align__(16) __nv_bfloat16 g_pre_hi[N_B * S_TOT * C_DIM];  // sampled (n,s,c)
__device__ __align__(16) __nv_bfloat16 g_pre_lo[N_B * S_TOT * C_DIM];
__device__ __align__(16) __nv_bfloat16 g_Wv_hi[C_DIM * C_DIM];
__device__ __align__(16) __nv_bfloat16 g_Wv_lo[C_DIM * C_DIM];
__device__ __align__(16) __nv_bfloat16 g_Wo_hi[C_DIM * C_DIM];
__device__ __align__(16) __nv_bfloat16 g_Wo_lo[C_DIM * C_DIM];
__device__ __align__(16) __nv_bfloat16 g_Wc_hi[128 * C_DIM];           // [Wloc;Ww;0] padded
__device__ __align__(16) __nv_bfloat16 g_Wc_lo[128 * C_DIM];
__device__ __align__(16) float         g_bcat[128];                    // [bloc;bw;0]

// ---------------- PTX helpers (arch-generic, no 103a features) ----------------
__device__ __forceinline__ unsigned smem_u32(const void* p) {
    unsigned a;
    asm("{ .reg .u64 t; cvta.to.shared.u64 t, %1; cvt.u32.u64 %0, t; }" : "=r"(a) : "l"(p));
    return a;
}
__device__ __forceinline__ void cp16(unsigned dst, const void* src, int ok) {
    int sz = ok ? 16 : 0;
    asm volatile("cp.async.cg.shared.global [%0], [%1], 16, %2;"
                 :: "r"(dst), "l"(src), "r"(sz) : "memory");
}
#define CP_COMMIT() asm volatile("cp.async.commit_group;" ::: "memory")
#define CP_WAIT(n)  asm volatile("cp.async.wait_group %0;" :: "n"(n) : "memory")

#define LDSM4(r, addr) \
    asm volatile("ldmatrix.sync.aligned.m8n8.x4.shared.b16 {%0,%1,%2,%3}, [%4];" \
                 : "=r"((r)[0]), "=r"((r)[1]), "=r"((r)[2]), "=r"((r)[3]) : "r"(addr))

__device__ __forceinline__ void mma_bf16(float* d, const unsigned* a, const unsigned* b) {
    asm volatile(
        "mma.sync.aligned.m16n8k16.row.col.f32.bf16.bf16.f32 "
        "{%0,%1,%2,%3}, {%4,%5,%6,%7}, {%8,%9}, {%0,%1,%2,%3};"
        : "+f"(d[0]), "+f"(d[1]), "+f"(d[2]), "+f"(d[3])
        : "r"(a[0]), "r"(a[1]), "r"(a[2]), "r"(a[3]), "r"(b[0]), "r"(b[1]));
}

// smem geometry: padded rows (32 halves + 8 pad = 80 B) -> conflict-free ldmatrix
#define KC          32
#define ROW_B       80
#define BUF_B       (128 * ROW_B)      // 10240
#define STAGE_B     (4 * BUF_B)        // 40960  (Ah, Al, Bh, Bl)
#define GEMM_SMEM   (2 * STAGE_B)      // 81920
#define NCHUNK      (C_DIM / KC)       // 16

// =====================================================================
// prep: fp32 -> bf16 hi/lo elementwise (Wv at y=0, Wo at y=1)
// =====================================================================
__global__ void k_split2(const float* __restrict__ Wv, const float* __restrict__ Wo) {
    int i = blockIdx.x * 256 + threadIdx.x;
    const float* src = blockIdx.y ? Wo : Wv;
    __nv_bfloat16* hi = blockIdx.y ? g_Wo_hi : g_Wv_hi;
    __nv_bfloat16* lo = blockIdx.y ? g_Wo_lo : g_Wv_lo;
    float v = src[i];
    __nv_bfloat16 h = __float2bfloat16(v);
    hi[i] = h;
    lo[i] = __float2bfloat16(v - __bfloat162float(h));
}

// =====================================================================
// prep: [Wloc(64);Ww(32);0(32)] -> g_Wc hi/lo (128x512), g_bcat
// =====================================================================
__global__ void k_prep_w(const float* __restrict__ Wloc, const float* __restrict__ bloc,
                         const float* __restrict__ Ww,   const float* __restrict__ bw) {
    int r = blockIdx.x, c = threadIdx.x;
    float v = (r < 64) ? Wloc[(size_t)r * C_DIM + c]
            : (r < 96) ? Ww[(size_t)(r - 64) * C_DIM + c] : 0.0f;
    __nv_bfloat16 h = __float2bfloat16(v);
    g_Wc_hi[(size_t)r * C_DIM + c] = h;
    g_Wc_lo[(size_t)r * C_DIM + c] = __float2bfloat16(v - __bfloat162float(h));
    if (c == 0)
        g_bcat[r] = (r < 64) ? bloc[r] : (r < 96) ? bw[r - 64] : 0.0f;
}

// =====================================================================
// prep: x,pos [n][k][s] fp32 -> xT and (x+pos)T hi/lo bf16 (32x32 transpose)
// =====================================================================
__global__ void k_convX(const float* __restrict__ x, const float* __restrict__ pos,
                        const unsigned char* __restrict__ mask) {
    __shared__ float tx[32][33], tp[32][33];
    const int s0 = blockIdx.x * 32, k0 = blockIdx.y * 32, n = blockIdx.z;
    const int txi = threadIdx.x, tyi = threadIdx.y;
#pragma unroll
    for (int r = 0; r < 4; r++) {
        int k = k0 + tyi + r * 8, s = s0 + txi;
        size_t gi = ((size_t)n * C_DIM + k) * S_TOT + s;
        tx[tyi + r * 8][txi] = (s < S_TOT) ? x[gi] : 0.0f;
        tp[tyi + r * 8][txi] = (s < S_TOT) ? pos[gi] : 0.0f;
    }
    __syncthreads();
#pragma unroll
    for (int r = 0; r < 4; r++) {
        int s = s0 + tyi + r * 8, k = k0 + txi;
        if (s < S_TOT) {
            float xv = tx[txi][tyi + r * 8];
            float pv = tp[txi][tyi + r * 8];
            bool m = mask[(size_t)n * S_TOT + s] != 0;
            size_t o = ((size_t)n * S_TOT + s) * C_DIM + k;
            __nv_bfloat16 h = __float2bfloat16(xv);
            g_xT_hi[o] = h;
            g_xT_lo[o] = __float2bfloat16(xv - __bfloat162float(h));
            float xp = m ? 0.0f : (xv + pv);
            __nv_bfloat16 hp = __float2bfloat16(xp);
            g_xpT_hi[o] = hp;
            g_xpT_lo[o] = __float2bfloat16(xp - __bfloat162float(hp));
        }
    }
}

// =====================================================================
// HMMA GEMM, bf16 2-term split (ah*bh + ah*bl + al*bh), fp32 reg acc.
// MODE 0: D[s][c] = xT @ Wv^T   -> g_value (+bv, mask)   A=xT(s),  B=Wv(c)
// MODE 1: D[c][s] = Wo @ pre^T  -> out (scale*(v+bo))    A=Wo(c),  B=pre(s)
// MODE 2: D[s][r] = xpT @ Wc^T  -> g_offw (+bcat)        A=xpT(s), B=Wc(r,128)
// Block tile 128(m) x 128(n); 128 threads = 4 warps of 64(m) x 64(n)
// (A-dup = B-dup = 2 in smem -> smem-per-MAC cut 25% vs 8x(32x64)).
// =====================================================================
template<int MODE>
__global__ void __launch_bounds__(128, 2) k_gemm(
    const unsigned char* __restrict__ mask,
    const float* __restrict__ bias,
    const float* __restrict__ scl,
    float* __restrict__ outp)
{
    extern __shared__ char smem[];
    const int t = threadIdx.x, lane = t & 31, wid = t >> 5;
    const int mb = blockIdx.x * 128;
    const int nb = blockIdx.y * 128;
    const int n  = blockIdx.z;
    const unsigned sbase = smem_u32(smem);

    const __nv_bfloat16 *Ah, *Al, *Bh, *Bl;
    int a_lim, b_lim;
    if (MODE == 0) {
        Ah = g_xT_hi + (size_t)n * S_TOT * C_DIM;
        Al = g_xT_lo + (size_t)n * S_TOT * C_DIM;
        a_lim = S_TOT;
        Bh = g_Wv_hi; Bl = g_Wv_lo; b_lim = C_DIM;
    } else if (MODE == 1) {
        Ah = g_Wo_hi; Al = g_Wo_lo; a_lim = C_DIM;
        Bh = g_pre_hi + (size_t)n * S_TOT * C_DIM;
        Bl = g_pre_lo + (size_t)n * S_TOT * C_DIM;
        b_lim = S_TOT;
    } else {
        Ah = g_xpT_hi + (size_t)n * S_TOT * C_DIM;
        Al = g_xpT_lo + (size_t)n * S_TOT * C_DIM;
        a_lim = S_TOT;
        Bh = g_Wc_hi; Bl = g_Wc_lo; b_lim = 128;
    }

    // loader (128 threads): row = t>>2 (+32*i), seg = t&3 (4 x 16B = 64B/row)
    const int l_row0 = t >> 2, l_seg = t & 3;
#define ISSUE(chunk)                                                                   \
    {                                                                                  \
        const int k0 = (chunk) * KC;                                                   \
        const unsigned st_ = sbase + ((chunk) & 1) * STAGE_B;                          \
        _Pragma("unroll")                                                              \
        for (int i_ = 0; i_ < 4; i_++) {                                               \
            int row = l_row0 + i_ * 32;                                                \
            unsigned doff = row * ROW_B + l_seg * 16;                                  \
            int ra = mb + row; int oka = ra < a_lim; ra = oka ? ra : 0;                \
            size_t ga = (size_t)ra * C_DIM + k0 + l_seg * 8;                           \
            cp16(st_ + 0 * BUF_B + doff, Ah + ga, oka);                                \
            cp16(st_ + 1 * BUF_B + doff, Al + ga, oka);                                \
            int rb = nb + row; int okb = rb < b_lim; rb = okb ? rb : 0;                \
            size_t gb = (size_t)rb * C_DIM + k0 + l_seg * 8;                           \
            cp16(st_ + 2 * BUF_B + doff, Bh + gb, okb);                                \
            cp16(st_ + 3 * BUF_B + doff, Bl + gb, okb);                                \
        }                                                                              \
        CP_COMMIT();                                                                   \
    }

    const int wm = (wid >> 1) * 64;   // 2 warp rows (m)
    const int wn = (wid & 1) * 64;    // 2 warp cols (n)
    const unsigned aoff = (wm + (lane & 15)) * ROW_B + ((lane & 16) ? 16 : 0);
    const unsigned boff = (wn + (lane & 7) + ((lane & 16) ? 8 : 0)) * ROW_B
                        + ((lane & 8) ? 16 : 0);

    float acc[4][8][4];
#pragma unroll
    for (int a = 0; a < 4; a++)
#pragma unroll
        for (int b = 0; b < 8; b++)
#pragma unroll
            for (int j = 0; j < 4; j++) acc[a][b][j] = 0.0f;

    ISSUE(0);
    for (int c = 0; c < NCHUNK; c++) {
        if (c + 1 < NCHUNK) { ISSUE(c + 1); CP_WAIT(1); }
        else                { CP_WAIT(0); }
        __syncthreads();
        const unsigned st = sbase + (c & 1) * STAGE_B;
#pragma unroll
        for (int ks = 0; ks < 2; ks++) {
            unsigned ahi[4][4], alo[4][4];
#pragma unroll
            for (int mt = 0; mt < 4; mt++) {
                LDSM4(ahi[mt], st + 0 * BUF_B + aoff + mt * (16 * ROW_B) + ks * 32);
                LDSM4(alo[mt], st + 1 * BUF_B + aoff + mt * (16 * ROW_B) + ks * 32);
            }
#pragma unroll
            for (int g = 0; g < 4; g++) {
                unsigned bh[4], bl[4];
                LDSM4(bh, st + 2 * BUF_B + boff + g * (16 * ROW_B) + ks * 32);
                LDSM4(bl, st + 3 * BUF_B + boff + g * (16 * ROW_B) + ks * 32);
#pragma unroll
                for (int j = 0; j < 2; j++) {
#pragma unroll
                    for (int mt = 0; mt < 4; mt++) {
                        float* d = acc[mt][g * 2 + j];
                        mma_bf16(d, ahi[mt], &bh[2 * j]);
                        mma_bf16(d, ahi[mt], &bl[2 * j]);
                        mma_bf16(d, alo[mt], &bh[2 * j]);
                    }
                }
            }
        }
        __syncthreads();
    }
#undef ISSUE

    // ---- epilogue: n-dim is the contiguous store dim in all modes ----
    if (MODE == 0) {
        const unsigned char* mk = mask + (size_t)n * S_TOT;
        float* dst = g_value + (size_t)n * S_TOT * C_DIM;
#pragma unroll
        for (int mt = 0; mt < 4; mt++) {
            int s0 = mb + wm + mt * 16 + (lane >> 2);
#pragma unroll
            for (int tn = 0; tn < 8; tn++) {
                int cc = nb + wn + tn * 8 + 2 * (lane & 3);
                float2 bp = *(const float2*)(bias + cc);
                float* d = acc[mt][tn];
                if (s0 < S_TOT) {
                    float m = mk[s0] ? 0.0f : 1.0f;
                    float2 v; v.x = m * (d[0] + bp.x); v.y = m * (d[1] + bp.y);
                    *(float2*)(dst + (size_t)s0 * C_DIM + cc) = v;
                }
                int s1 = s0 + 8;
                if (s1 < S_TOT) {
                    float m = mk[s1] ? 0.0f : 1.0f;
                    float2 v; v.x = m * (d[2] + bp.x); v.y = m * (d[3] + bp.y);
                    *(float2*)(dst + (size_t)s1 * C_DIM + cc) = v;
                }
            }
        }
    } else if (MODE == 1) {
#pragma unroll
        for (int mt = 0; mt < 4; mt++) {
            int c0 = mb + wm + mt * 16 + (lane >> 2);
            int c1 = c0 + 8;
            float sc0 = scl[c0], b0 = bias[c0];
            float sc1 = scl[c1], b1 = bias[c1];
            float* r0 = outp + ((size_t)n * C_DIM + c0) * S_TOT;
            float* r1 = outp + ((size_t)n * C_DIM + c1) * S_TOT;
#pragma unroll
            for (int tn = 0; tn < 8; tn++) {
                int ss = nb + wn + tn * 8 + 2 * (lane & 3);
                float* d = acc[mt][tn];
                if (ss < S_TOT) {   // S_TOT even, ss even -> pair fully in-bounds
                    float2 v0; v0.x = sc0 * (d[0] + b0); v0.y = sc0 * (d[1] + b0);
                    *(float2*)(r0 + ss) = v0;
                    float2 v1; v1.x = sc1 * (d[2] + b1); v1.y = sc1 * (d[3] + b1);
                    *(float2*)(r1 + ss) = v1;
                }
            }
        }
    } else {
        float* dst = g_offw + (size_t)n * S_TOT * 128;
#pragma unroll
        for (int mt = 0; mt < 4; mt++) {
            int s0 = mb + wm + mt * 16 + (lane >> 2);
#pragma unroll
            for (int tn = 0; tn < 8; tn++) {
                int cc = wn + tn * 8 + 2 * (lane & 3);
                float2 bp = *(const float2*)(bias + cc);
                float* d = acc[mt][tn];
                if (s0 < S_TOT) {
                    float2 v; v.x = d[0] + bp.x; v.y = d[1] + bp.y;
                    *(float2*)(dst + (size_t)s0 * 128 + cc) = v;
                }
                int s1 = s0 + 8;
                if (s1 < S_TOT) {
                    float2 v; v.x = d[2] + bp.x; v.y = d[3] + bp.y;
                    *(float2*)(dst + (size_t)s1 * 128 + cc) = v;
                }
            }
        }
    }
}

// =====================================================================
// k_gather: read logits from g_offw, softmax over levels, bilinear-sample
// g_value, weighted sum -> g_pre_hi/lo. One warp per query, 8 warps/block.
// =====================================================================
__global__ void __launch_bounds__(256) k_gather(
    const float* __restrict__ vsz, const float* __restrict__ vsc)
{
    const int lvl = blockIdx.y, n = blockIdx.z;
    const int H = c_H[lvl], W = c_W[lvl];
    const int L = H * W, loff = c_off[lvl];
    const int wid = threadIdx.x >> 5, lane = threadIdx.x & 31;
    const int gq = blockIdx.x * 8 + wid;
    if (gq >= L) return;

    const float scx = 2.0f * vsc[((size_t)n * FL_N + lvl) * 2 + 0] / vsz[((size_t)n * FL_N + lvl) * 2 + 0];
    const float scy = 2.0f * vsc[((size_t)n * FL_N + lvl) * 2 + 1] / vsz[((size_t)n * FL_N + lvl) * 2 + 1];

    int row = gq / W, col = gq - row * W;
    float prex = col + 0.5f, prey = row + 0.5f;
    int s_q = loff + gq;

    const float* ow = g_offw + (size_t)(n * S_TOT + s_q) * 128;
    float v0 = ow[lane], v1 = ow[32 + lane], v2 = ow[64 + lane];

    for (int m = 0; m < 8; m++) {
        float vo = (m < 4) ? v0 : v1;
        float l0 = __shfl_sync(0xFFFFFFFFu, v2, m * 4 + 0);
        float l1 = __shfl_sync(0xFFFFFFFFu, v2, m * 4 + 1);
        float l2 = __shfl_sync(0xFFFFFFFFu, v2, m * 4 + 2);
        float l3 = __shfl_sync(0xFFFFFFFFu, v2, m * 4 + 3);
        float mx = fmaxf(fmaxf(l0, l1), fmaxf(l2, l3));
        float e0 = __expf(l0 - mx), e1 = __expf(l1 - mx);
        float e2 = __expf(l2 - mx), e3 = __expf(l3 - mx);
        float inv = 1.0f / (e0 + e1 + e2 + e3);
        float wgt[4] = {e0 * inv, e1 * inv, e2 * inv, e3 * inv};

        float a0 = 0.0f, a1 = 0.0f;
#pragma unroll
        for (int f = 0; f < 4; f++) {
            int Hf = c_H[f], Wf = c_W[f], lof = c_off[f];
            int rbase = (m * 8 + f * 2) & 31;
            float offx = __shfl_sync(0xFFFFFFFFu, vo, rbase);
            float offy = __shfl_sync(0xFFFFFFFFu, vo, rbase + 1);
            float xx = (offx + prex) * (scx * 0.5f * (float)Wf) - 0.5f;
            float yy = (offy + prey) * (scy * 0.5f * (float)Hf) - 0.5f;
            float x0f = floorf(xx), y0f = floorf(yy);
            int ix0 = (int)x0f, iy0 = (int)y0f;
            float wx1 = xx - x0f, wy1 = yy - y0f;
            float wx0 = 1.0f - wx1, wy0 = 1.0f - wy1;
            float wf = wgt[f];
            const float* vb = g_value + ((size_t)n * S_TOT + lof) * C_DIM + m * 64 + lane * 2;
#define CORNER(ix, iy, cw) \
            if ((unsigned)(ix) < (unsigned)Wf && (unsigned)(iy) < (unsigned)Hf) { \
                float2 v = *(const float2*)(vb + ((size_t)(iy) * Wf + (ix)) * C_DIM); \
                float w_ = wf * (cw); a0 += w_ * v.x; a1 += w_ * v.y; }
            CORNER(ix0,     iy0,     wx0 * wy0)
            CORNER(ix0 + 1, iy0,     wx1 * wy0)
            CORNER(ix0,     iy0 + 1, wx0 * wy1)
            CORNER(ix0 + 1, iy0 + 1, wx1 * wy1)
#undef CORNER
        }
        __nv_bfloat162 hv, lv;
        hv.x = __float2bfloat16(a0);
        lv.x = __float2bfloat16(a0 - __bfloat162float(hv.x));
        hv.y = __float2bfloat16(a1);
        lv.y = __float2bfloat16(a1 - __bfloat162float(hv.y));
        size_t oi = (size_t)(n * S_TOT + s_q) * (C_DIM / 2) + m * 32 + lane;
        ((__nv_bfloat162*)g_pre_hi)[oi] = hv;
        ((__nv_bfloat162*)g_pre_lo)[oi] = lv;
    }
}

extern "C" void kernel_launch(void* const* d_in, const int* in_sizes, int n_in,
                              void* d_out, int out_size) {
    const float* x    = (const float*)d_in[0];
    const float* pos  = (const float*)d_in[1];
    const unsigned char* mask = (const unsigned char*)d_in[2];
    const float* vsz  = (const float*)d_in[3];
    const float* vsc  = (const float*)d_in[4];
    const float* Wv   = (const float*)d_in[5];
    const float* bv   = (const float*)d_in[6];
    const float* Wloc = (const float*)d_in[7];
    const float* bloc = (const float*)d_in[8];
    const float* Ww   = (const float*)d_in[9];
    const float* bw   = (const float*)d_in[10];
    const float* Wo   = (const float*)d_in[11];
    const float* bo   = (const float*)d_in[12];
    const float* scale = (const float*)d_in[13];
    float* out = (float*)d_out;

    cudaFuncSetAttribute(k_gemm<0>, cudaFuncAttributeMaxDynamicSharedMemorySize, GEMM_SMEM);
    cudaFuncSetAttribute(k_gemm<1>, cudaFuncAttributeMaxDynamicSharedMemorySize, GEMM_SMEM);
    cudaFuncSetAttribute(k_gemm<2>, cudaFuncAttributeMaxDynamicSharedMemorySize, GEMM_SMEM);

    void* p_bcat;
    cudaGetSymbolAddress(&p_bcat, g_bcat);

    // prep: split weights, build concat proj weights, transpose+split x / x+pos
    k_split2<<<dim3(1024, 2), 256>>>(Wv, Wo);
    k_prep_w<<<128, 512>>>(Wloc, bloc, Ww, bw);
    k_convX<<<dim3((S_TOT + 31) / 32, C_DIM / 32, N_B), dim3(32, 8)>>>(x, pos, mask);

    // value GEMM: D[s][c]
    k_gemm<0><<<dim3((S_TOT + 127) / 128, C_DIM / 128, N_B), 128, GEMM_SMEM>>>(
        mask, bv, nullptr, nullptr);

    // offset/weight logits GEMM: D[s][r], N = 128
    k_gemm<2><<<dim3((S_TOT + 127) / 128, 1, N_B), 128, GEMM_SMEM>>>(
        mask, (const float*)p_bcat, nullptr, nullptr);

    // deformable sampling (gather-only)
    k_gather<<<dim3(1250, FL_N, N_B), 256>>>(vsz, vsc);

    // output GEMM: D[c][s]
    k_gemm<1><<<dim3(C_DIM / 128, (S_TOT + 127) / 128, N_B), 128, GEMM_SMEM>>>(
        mask, bo, scale, out);
}

// round 14
// speedup vs baseline: 2.2625x; 1.1714x over previous
#include <cuda_runtime.h>
#include <cuda_fp16.h>
#include <math.h>

#define N_B    2
#define C_DIM  512
#define S_TOT  13294
#define FL_N   4

// Level geometry (H, W, flat offset in s)
__constant__ int c_H[4]   = {100, 50, 25, 13};
__constant__ int c_W[4]   = {100, 50, 25, 13};
__constant__ int c_off[4] = {0, 10000, 12500, 13125};

// ---------------- device scratch ----------------
__device__ __align__(16) float  g_value[N_B * S_TOT * C_DIM];   // fp32, (n,s,c)
__device__ __align__(16) float  g_offw[N_B * S_TOT * 128];      // fp32 logits per query
__device__ __align__(16) __half g_xT_hi[N_B * S_TOT * C_DIM];   // x^T (n,s,k) fp16 split
__device__ __align__(16) __half g_xT_lo[N_B * S_TOT * C_DIM];
__device__ __align__(16) __half g_xpT_hi[N_B * S_TOT * C_DIM];  // (x+pos)^T fp16 split
__device__ __align__(16) __half g_xpT_lo[N_B * S_TOT * C_DIM];
__device__ __align__(16) __half g_pre_hi[N_B * S_TOT * C_DIM];  // sampled (n,s,c) fp16 split
__device__ __align__(16) __half g_pre_lo[N_B * S_TOT * C_DIM];
__device__ __align__(16) __half g_Wv[C_DIM * C_DIM];            // plain fp16 weights
__device__ __align__(16) __half g_Wo[C_DIM * C_DIM];
__device__ __align__(16) __half g_Wc[128 * C_DIM];              // [Wloc;Ww;0] padded
__device__ __align__(16) float  g_bcat[128];                    // [bloc;bw;0]

// ---------------- PTX helpers (arch-generic, no 103a features) ----------------
__device__ __forceinline__ unsigned smem_u32(const void* p) {
    unsigned a;
    asm("{ .reg .u64 t; cvta.to.shared.u64 t, %1; cvt.u32.u64 %0, t; }" : "=r"(a) : "l"(p));
    return a;
}
__device__ __forceinline__ void cp16(unsigned dst, const void* src, int ok) {
    int sz = ok ? 16 : 0;
    asm volatile("cp.async.cg.shared.global [%0], [%1], 16, %2;"
                 :: "r"(dst), "l"(src), "r"(sz) : "memory");
}
#define CP_COMMIT() asm volatile("cp.async.commit_group;" ::: "memory")
#define CP_WAIT(n)  asm volatile("cp.async.wait_group %0;" :: "n"(n) : "memory")

#define LDSM4(r, addr) \
    asm volatile("ldmatrix.sync.aligned.m8n8.x4.shared.b16 {%0,%1,%2,%3}, [%4];" \
                 : "=r"((r)[0]), "=r"((r)[1]), "=r"((r)[2]), "=r"((r)[3]) : "r"(addr))

__device__ __forceinline__ void mma_f16(float* d, const unsigned* a, const unsigned* b) {
    asm volatile(
        "mma.sync.aligned.m16n8k16.row.col.f32.f16.f16.f32 "
        "{%0,%1,%2,%3}, {%4,%5,%6,%7}, {%8,%9}, {%0,%1,%2,%3};"
        : "+f"(d[0]), "+f"(d[1]), "+f"(d[2]), "+f"(d[3])
        : "r"(a[0]), "r"(a[1]), "r"(a[2]), "r"(a[3]), "r"(b[0]), "r"(b[1]));
}

// smem geometry: padded rows (32 halves + 8 pad = 80 B) -> conflict-free ldmatrix
#define KC          32
#define ROW_B       80
#define BUF_B       (128 * ROW_B)      // 10240
#define STAGE_B     (3 * BUF_B)        // 30720  (SplitHi, SplitLo, Plain)
#define GEMM_SMEM   (2 * STAGE_B)      // 61440
#define NCHUNK      (C_DIM / KC)       // 16

// =====================================================================
// prep: fp32 -> plain fp16 (Wv at y=0, Wo at y=1)
// =====================================================================
__global__ void k_cvt(const float* __restrict__ Wv, const float* __restrict__ Wo) {
    int i = blockIdx.x * 256 + threadIdx.x;
    const float* src = blockIdx.y ? Wo : Wv;
    __half* dst = blockIdx.y ? g_Wo : g_Wv;
    dst[i] = __float2half_rn(src[i]);
}

// =====================================================================
// prep: [Wloc(64);Ww(32);0(32)] -> g_Wc plain fp16 (128x512), g_bcat
// =====================================================================
__global__ void k_prep_w(const float* __restrict__ Wloc, const float* __restrict__ bloc,
                         const float* __restrict__ Ww,   const float* __restrict__ bw) {
    int r = blockIdx.x, c = threadIdx.x;
    float v = (r < 64) ? Wloc[(size_t)r * C_DIM + c]
            : (r < 96) ? Ww[(size_t)(r - 64) * C_DIM + c] : 0.0f;
    g_Wc[(size_t)r * C_DIM + c] = __float2half_rn(v);
    if (c == 0)
        g_bcat[r] = (r < 64) ? bloc[r] : (r < 96) ? bw[r - 64] : 0.0f;
}

// =====================================================================
// prep: x,pos [n][k][s] fp32 -> xT and (x+pos)T fp16 hi/lo (32x32 transpose)
// =====================================================================
__global__ void k_convX(const float* __restrict__ x, const float* __restrict__ pos,
                        const unsigned char* __restrict__ mask) {
    __shared__ float tx[32][33], tp[32][33];
    const int s0 = blockIdx.x * 32, k0 = blockIdx.y * 32, n = blockIdx.z;
    const int txi = threadIdx.x, tyi = threadIdx.y;
#pragma unroll
    for (int r = 0; r < 4; r++) {
        int k = k0 + tyi + r * 8, s = s0 + txi;
        size_t gi = ((size_t)n * C_DIM + k) * S_TOT + s;
        tx[tyi + r * 8][txi] = (s < S_TOT) ? x[gi] : 0.0f;
        tp[tyi + r * 8][txi] = (s < S_TOT) ? pos[gi] : 0.0f;
    }
    __syncthreads();
#pragma unroll
    for (int r = 0; r < 4; r++) {
        int s = s0 + tyi + r * 8, k = k0 + txi;
        if (s < S_TOT) {
            float xv = tx[txi][tyi + r * 8];
            float pv = tp[txi][tyi + r * 8];
            bool m = mask[(size_t)n * S_TOT + s] != 0;
            size_t o = ((size_t)n * S_TOT + s) * C_DIM + k;
            __half h = __float2half_rn(xv);
            g_xT_hi[o] = h;
            g_xT_lo[o] = __float2half_rn(xv - __half2float(h));
            float xp = m ? 0.0f : (xv + pv);
            __half hp = __float2half_rn(xp);
            g_xpT_hi[o] = hp;
            g_xpT_lo[o] = __float2half_rn(xp - __half2float(hp));
        }
    }
}

// =====================================================================
// HMMA GEMM, fp16 2-term: activation split (hi+lo, exact), weight plain fp16.
// D = Xh*W + Xl*W  (2 mma per tile instead of 3)
// MODE 0: D[s][c] = xT @ Wv^T   -> g_value (+bv, mask)   split=A(xT),  plain=B(Wv)
// MODE 1: D[c][s] = Wo @ pre^T  -> out (scale*(v+bo))    split=B(pre), plain=A(Wo)
// MODE 2: D[s][r] = xpT @ Wc^T  -> g_offw (+bcat)        split=A(xpT), plain=B(Wc)
// Block tile 128(m) x 128(n); 128 threads = 4 warps of 64(m) x 64(n).
// =====================================================================
template<int MODE>
__global__ void __launch_bounds__(128, 2) k_gemm(
    const unsigned char* __restrict__ mask,
    const float* __restrict__ bias,
    const float* __restrict__ scl,
    float* __restrict__ outp)
{
    extern __shared__ char smem[];
    const int t = threadIdx.x, lane = t & 31, wid = t >> 5;
    const int mb = blockIdx.x * 128;
    const int nb = blockIdx.y * 128;
    const int n  = blockIdx.z;
    const unsigned sbase = smem_u32(smem);

    // X = split operand (hi/lo), Y = plain operand
    const __half *Xh, *Xl, *Yp;
    int x_row0, x_lim, y_row0, y_lim;
    if (MODE == 0) {
        Xh = g_xT_hi + (size_t)n * S_TOT * C_DIM;
        Xl = g_xT_lo + (size_t)n * S_TOT * C_DIM;
        x_row0 = mb; x_lim = S_TOT;
        Yp = g_Wv; y_row0 = nb; y_lim = C_DIM;
    } else if (MODE == 1) {
        Xh = g_pre_hi + (size_t)n * S_TOT * C_DIM;
        Xl = g_pre_lo + (size_t)n * S_TOT * C_DIM;
        x_row0 = nb; x_lim = S_TOT;
        Yp = g_Wo; y_row0 = mb; y_lim = C_DIM;
    } else {
        Xh = g_xpT_hi + (size_t)n * S_TOT * C_DIM;
        Xl = g_xpT_lo + (size_t)n * S_TOT * C_DIM;
        x_row0 = mb; x_lim = S_TOT;
        Yp = g_Wc; y_row0 = nb; y_lim = 128;
    }

    // loader (128 threads): row = t>>2 (+32*i), seg = t&3 (4 x 16B = 64B/row)
    const int l_row0 = t >> 2, l_seg = t & 3;
#define ISSUE(chunk)                                                                   \
    {                                                                                  \
        const int k0 = (chunk) * KC;                                                   \
        const unsigned st_ = sbase + ((chunk) & 1) * STAGE_B;                          \
        _Pragma("unroll")                                                              \
        for (int i_ = 0; i_ < 4; i_++) {                                               \
            int row = l_row0 + i_ * 32;                                                \
            unsigned doff = row * ROW_B + l_seg * 16;                                  \
            int rx = x_row0 + row; int okx = rx < x_lim; rx = okx ? rx : 0;            \
            size_t gx = (size_t)rx * C_DIM + k0 + l_seg * 8;                           \
            cp16(st_ + 0 * BUF_B + doff, Xh + gx, okx);                                \
            cp16(st_ + 1 * BUF_B + doff, Xl + gx, okx);                                \
            int ry = y_row0 + row; int oky = ry < y_lim; ry = oky ? ry : 0;            \
            size_t gy = (size_t)ry * C_DIM + k0 + l_seg * 8;                           \
            cp16(st_ + 2 * BUF_B + doff, Yp + gy, oky);                                \
        }                                                                              \
        CP_COMMIT();                                                                   \
    }

    const int wm = (wid >> 1) * 64;   // 2 warp rows (m)
    const int wn = (wid & 1) * 64;    // 2 warp cols (n)
    const unsigned aoff = (wm + (lane & 15)) * ROW_B + ((lane & 16) ? 16 : 0);
    const unsigned boff = (wn + (lane & 7) + ((lane & 16) ? 8 : 0)) * ROW_B
                        + ((lane & 8) ? 16 : 0);
    // A-side buffers: MODE1 -> plain (PL at 2*BUF_B); else split (SP0/SP1)
    // B-side buffers: MODE1 -> split; else plain

    float acc[4][8][4];
#pragma unroll
    for (int a = 0; a < 4; a++)
#pragma unroll
        for (int b = 0; b < 8; b++)
#pragma unroll
            for (int j = 0; j < 4; j++) acc[a][b][j] = 0.0f;

    ISSUE(0);
    for (int c = 0; c < NCHUNK; c++) {
        if (c + 1 < NCHUNK) { ISSUE(c + 1); CP_WAIT(1); }
        else                { CP_WAIT(0); }
        __syncthreads();
        const unsigned st = sbase + (c & 1) * STAGE_B;
#pragma unroll
        for (int ks = 0; ks < 2; ks++) {
            if (MODE == 1) {
                // A plain (Wo), B split (pre)
                unsigned a4[4][4];
#pragma unroll
                for (int mt = 0; mt < 4; mt++)
                    LDSM4(a4[mt], st + 2 * BUF_B + aoff + mt * (16 * ROW_B) + ks * 32);
#pragma unroll
                for (int g = 0; g < 4; g++) {
                    unsigned bh[4], bl[4];
                    LDSM4(bh, st + 0 * BUF_B + boff + g * (16 * ROW_B) + ks * 32);
                    LDSM4(bl, st + 1 * BUF_B + boff + g * (16 * ROW_B) + ks * 32);
#pragma unroll
                    for (int j = 0; j < 2; j++) {
#pragma unroll
                        for (int mt = 0; mt < 4; mt++) {
                            float* d = acc[mt][g * 2 + j];
                            mma_f16(d, a4[mt], &bh[2 * j]);
                            mma_f16(d, a4[mt], &bl[2 * j]);
                        }
                    }
                }
            } else {
                // A split (xT/xpT), B plain (Wv/Wc)
                unsigned ahi[4][4], alo[4][4];
#pragma unroll
                for (int mt = 0; mt < 4; mt++) {
                    LDSM4(ahi[mt], st + 0 * BUF_B + aoff + mt * (16 * ROW_B) + ks * 32);
                    LDSM4(alo[mt], st + 1 * BUF_B + aoff + mt * (16 * ROW_B) + ks * 32);
                }
#pragma unroll
                for (int g = 0; g < 4; g++) {
                    unsigned b4[4];
                    LDSM4(b4, st + 2 * BUF_B + boff + g * (16 * ROW_B) + ks * 32);
#pragma unroll
                    for (int j = 0; j < 2; j++) {
#pragma unroll
                        for (int mt = 0; mt < 4; mt++) {
                            float* d = acc[mt][g * 2 + j];
                            mma_f16(d, ahi[mt], &b4[2 * j]);
                            mma_f16(d, alo[mt], &b4[2 * j]);
                        }
                    }
                }
            }
        }
        __syncthreads();
    }
#undef ISSUE

    // ---- epilogue: n-dim is the contiguous store dim in all modes ----
    if (MODE == 0) {
        const unsigned char* mk = mask + (size_t)n * S_TOT;
        float* dst = g_value + (size_t)n * S_TOT * C_DIM;
#pragma unroll
        for (int mt = 0; mt < 4; mt++) {
            int s0 = mb + wm + mt * 16 + (lane >> 2);
#pragma unroll
            for (int tn = 0; tn < 8; tn++) {
                int cc = nb + wn + tn * 8 + 2 * (lane & 3);
                float2 bp = *(const float2*)(bias + cc);
                float* d = acc[mt][tn];
                if (s0 < S_TOT) {
                    float m = mk[s0] ? 0.0f : 1.0f;
                    float2 v; v.x = m * (d[0] + bp.x); v.y = m * (d[1] + bp.y);
                    *(float2*)(dst + (size_t)s0 * C_DIM + cc) = v;
                }
                int s1 = s0 + 8;
                if (s1 < S_TOT) {
                    float m = mk[s1] ? 0.0f : 1.0f;
                    float2 v; v.x = m * (d[2] + bp.x); v.y = m * (d[3] + bp.y);
                    *(float2*)(dst + (size_t)s1 * C_DIM + cc) = v;
                }
            }
        }
    } else if (MODE == 1) {
#pragma unroll
        for (int mt = 0; mt < 4; mt++) {
            int c0 = mb + wm + mt * 16 + (lane >> 2);
            int c1 = c0 + 8;
            float sc0 = scl[c0], b0 = bias[c0];
            float sc1 = scl[c1], b1 = bias[c1];
            float* r0 = outp + ((size_t)n * C_DIM + c0) * S_TOT;
            float* r1 = outp + ((size_t)n * C_DIM + c1) * S_TOT;
#pragma unroll
            for (int tn = 0; tn < 8; tn++) {
                int ss = nb + wn + tn * 8 + 2 * (lane & 3);
                float* d = acc[mt][tn];
                if (ss < S_TOT) {   // S_TOT even, ss even -> pair fully in-bounds
                    float2 v0; v0.x = sc0 * (d[0] + b0); v0.y = sc0 * (d[1] + b0);
                    *(float2*)(r0 + ss) = v0;
                    float2 v1; v1.x = sc1 * (d[2] + b1); v1.y = sc1 * (d[3] + b1);
                    *(float2*)(r1 + ss) = v1;
                }
            }
        }
    } else {
        float* dst = g_offw + (size_t)n * S_TOT * 128;
#pragma unroll
        for (int mt = 0; mt < 4; mt++) {
            int s0 = mb + wm + mt * 16 + (lane >> 2);
#pragma unroll
            for (int tn = 0; tn < 8; tn++) {
                int cc = wn + tn * 8 + 2 * (lane & 3);
                float2 bp = *(const float2*)(bias + cc);
                float* d = acc[mt][tn];
                if (s0 < S_TOT) {
                    float2 v; v.x = d[0] + bp.x; v.y = d[1] + bp.y;
                    *(float2*)(dst + (size_t)s0 * 128 + cc) = v;
                }
                int s1 = s0 + 8;
                if (s1 < S_TOT) {
                    float2 v; v.x = d[2] + bp.x; v.y = d[3] + bp.y;
                    *(float2*)(dst + (size_t)s1 * 128 + cc) = v;
                }
            }
        }
    }
}

// =====================================================================
// k_gather: read logits from g_offw, softmax over levels, bilinear-sample
// g_value, weighted sum -> g_pre_hi/lo (fp16 split). Warp per query.
// =====================================================================
__global__ void __launch_bounds__(256) k_gather(
    const float* __restrict__ vsz, const float* __restrict__ vsc)
{
    const int lvl = blockIdx.y, n = blockIdx.z;
    const int H = c_H[lvl], W = c_W[lvl];
    const int L = H * W, loff = c_off[lvl];
    const int wid = threadIdx.x >> 5, lane = threadIdx.x & 31;
    const int gq = blockIdx.x * 8 + wid;
    if (gq >= L) return;

    const float scx = 2.0f * vsc[((size_t)n * FL_N + lvl) * 2 + 0] / vsz[((size_t)n * FL_N + lvl) * 2 + 0];
    const float scy = 2.0f * vsc[((size_t)n * FL_N + lvl) * 2 + 1] / vsz[((size_t)n * FL_N + lvl) * 2 + 1];

    int row = gq / W, col = gq - row * W;
    float prex = col + 0.5f, prey = row + 0.5f;
    int s_q = loff + gq;

    const float* ow = g_offw + (size_t)(n * S_TOT + s_q) * 128;
    float v0 = ow[lane], v1 = ow[32 + lane], v2 = ow[64 + lane];

    for (int m = 0; m < 8; m++) {
        float vo = (m < 4) ? v0 : v1;
        float l0 = __shfl_sync(0xFFFFFFFFu, v2, m * 4 + 0);
        float l1 = __shfl_sync(0xFFFFFFFFu, v2, m * 4 + 1);
        float l2 = __shfl_sync(0xFFFFFFFFu, v2, m * 4 + 2);
        float l3 = __shfl_sync(0xFFFFFFFFu, v2, m * 4 + 3);
        float mx = fmaxf(fmaxf(l0, l1), fmaxf(l2, l3));
        float e0 = __expf(l0 - mx), e1 = __expf(l1 - mx);
        float e2 = __expf(l2 - mx), e3 = __expf(l3 - mx);
        float inv = 1.0f / (e0 + e1 + e2 + e3);
        float wgt[4] = {e0 * inv, e1 * inv, e2 * inv, e3 * inv};

        float a0 = 0.0f, a1 = 0.0f;
#pragma unroll
        for (int f = 0; f < 4; f++) {
            int Hf = c_H[f], Wf = c_W[f], lof = c_off[f];
            int rbase = (m * 8 + f * 2) & 31;
            float offx = __shfl_sync(0xFFFFFFFFu, vo, rbase);
            float offy = __shfl_sync(0xFFFFFFFFu, vo, rbase + 1);
            float xx = (offx + prex) * (scx * 0.5f * (float)Wf) - 0.5f;
            float yy = (offy + prey) * (scy * 0.5f * (float)Hf) - 0.5f;
            float x0f = floorf(xx), y0f = floorf(yy);
            int ix0 = (int)x0f, iy0 = (int)y0f;
            float wx1 = xx - x0f, wy1 = yy - y0f;
            float wx0 = 1.0f - wx1, wy0 = 1.0f - wy1;
            float wf = wgt[f];
            const float* vb = g_value + ((size_t)n * S_TOT + lof) * C_DIM + m * 64 + lane * 2;
#define CORNER(ix, iy, cw) \
            if ((unsigned)(ix) < (unsigned)Wf && (unsigned)(iy) < (unsigned)Hf) { \
                float2 v = *(const float2*)(vb + ((size_t)(iy) * Wf + (ix)) * C_DIM); \
                float w_ = wf * (cw); a0 += w_ * v.x; a1 += w_ * v.y; }
            CORNER(ix0,     iy0,     wx0 * wy0)
            CORNER(ix0 + 1, iy0,     wx1 * wy0)
            CORNER(ix0,     iy0 + 1, wx0 * wy1)
            CORNER(ix0 + 1, iy0 + 1, wx1 * wy1)
#undef CORNER
        }
        __half2 hv, lv;
        hv.x = __float2half_rn(a0);
        lv.x = __float2half_rn(a0 - __half2float(hv.x));
        hv.y = __float2half_rn(a1);
        lv.y = __float2half_rn(a1 - __half2float(hv.y));
        size_t oi = (size_t)(n * S_TOT + s_q) * (C_DIM / 2) + m * 32 + lane;
        ((__half2*)g_pre_hi)[oi] = hv;
        ((__half2*)g_pre_lo)[oi] = lv;
    }
}

extern "C" void kernel_launch(void* const* d_in, const int* in_sizes, int n_in,
                              void* d_out, int out_size) {
    const float* x    = (const float*)d_in[0];
    const float* pos  = (const float*)d_in[1];
    const unsigned char* mask = (const unsigned char*)d_in[2];
    const float* vsz  = (const float*)d_in[3];
    const float* vsc  = (const float*)d_in[4];
    const float* Wv   = (const float*)d_in[5];
    const float* bv   = (const float*)d_in[6];
    const float* Wloc = (const float*)d_in[7];
    const float* bloc = (const float*)d_in[8];
    const float* Ww   = (const float*)d_in[9];
    const float* bw   = (const float*)d_in[10];
    const float* Wo   = (const float*)d_in[11];
    const float* bo   = (const float*)d_in[12];
    const float* scale = (const float*)d_in[13];
    float* out = (float*)d_out;

    cudaFuncSetAttribute(k_gemm<0>, cudaFuncAttributeMaxDynamicSharedMemorySize, GEMM_SMEM);
    cudaFuncSetAttribute(k_gemm<1>, cudaFuncAttributeMaxDynamicSharedMemorySize, GEMM_SMEM);
    cudaFuncSetAttribute(k_gemm<2>, cudaFuncAttributeMaxDynamicSharedMemorySize, GEMM_SMEM);

    void* p_bcat;
    cudaGetSymbolAddress(&p_bcat, g_bcat);

    // prep: convert weights, build concat proj weights, transpose+split x / x+pos
    k_cvt<<<dim3(1024, 2), 256>>>(Wv, Wo);
    k_prep_w<<<128, 512>>>(Wloc, bloc, Ww, bw);
    k_convX<<<dim3((S_TOT + 31) / 32, C_DIM / 32, N_B), dim3(32, 8)>>>(x, pos, mask);

    // value GEMM: D[s][c]
    k_gemm<0><<<dim3((S_TOT + 127) / 128, C_DIM / 128, N_B), 128, GEMM_SMEM>>>(
        mask, bv, nullptr, nullptr);

    // offset/weight logits GEMM: D[s][r], N = 128
    k_gemm<2><<<dim3((S_TOT + 127) / 128, 1, N_B), 128, GEMM_SMEM>>>(
        mask, (const float*)p_bcat, nullptr, nullptr);

    // deformable sampling (gather-only)
    k_gather<<<dim3(1250, FL_N, N_B), 256>>>(vsz, vsc);

    // output GEMM: D[c][s]
    k_gemm<1><<<dim3(C_DIM / 128, (S_TOT + 127) / 128, N_B), 128, GEMM_SMEM>>>(
        mask, bo, scale, out);
}